// round 6
// baseline (speedup 1.0000x reference)
#include <cuda_runtime.h>
#include <math.h>
#include <stdint.h>

#define HW   (128 * 128)
#define Hh   128
#define Ww   128
#define Bb   4
#define Cc   64
#define Oo   64

// Scratch: offsets/mask planes [B][27][H][W]  (0..8 dy_k, 9..17 dx_k, 18..26 mask_k)
__device__ float g_scratch[Bb * 27 * HW];
// NHWC copy of x: [b][p][c], p = y*128+x, c contiguous (16 MB)
__device__ float g_xt[Bb * HW * Cc];
// Pre-split tf32 B matrices: [tap][o][pos(c)] interleaved so the (b0,b1) MMA
// fragment pair is one LDS.64:  pos(c) = (c>>3)*8 + (c&3)*2 + ((c>>2)&1)
__device__ float g_wbh[9 * 64 * 64];
__device__ float g_wbl[9 * 64 * 64];

typedef unsigned long long ull;

// ---------------- helpers ----------------
__device__ __forceinline__ uint32_t f2tf32(float s) {
    uint32_t r; asm("cvt.rna.tf32.f32 %0, %1;" : "=r"(r) : "f"(s)); return r;
}
__device__ __forceinline__ void ffma2(ull &acc, ull a, ull b) {
    asm("fma.rn.f32x2 %0, %1, %2, %0;" : "+l"(acc) : "l"(a), "l"(b));
}
__device__ __forceinline__ ull pack2(float x, float y) {
    ull r; asm("mov.b64 %0, {%1, %2};" : "=l"(r) : "f"(x), "f"(y)); return r;
}
__device__ __forceinline__ void unpack2(ull v, float &x, float &y) {
    asm("mov.b64 {%0, %1}, %2;" : "=f"(x), "=f"(y) : "l"(v));
}

#define MMA_TF32(d, a, b0, b1) \
    asm volatile("mma.sync.aligned.m16n8k8.row.col.f32.tf32.tf32.f32 " \
        "{%0,%1,%2,%3}, {%4,%5,%6,%7}, {%8,%9}, {%0,%1,%2,%3};" \
        : "+f"((d)[0]), "+f"((d)[1]), "+f"((d)[2]), "+f"((d)[3]) \
        : "r"((a)[0]), "r"((a)[1]), "r"((a)[2]), "r"((a)[3]), "r"(b0), "r"(b1))

// ---------------------------------------------------------------------------
// Kernel 1 (launched FIRST, fully self-contained): fused offset-conv (18) +
// mod-conv (9) + 2*sigmoid. Stages ALL transposed weights into smem once:
// ws[(k*64+c)*28 + t],  t: 0..17 offset-out, 18..26 mod-out, 27 pad.
// ---------------------------------------------------------------------------
#define OFF_SMEM_FLOATS (9 * 64 * 28)    // 16128 floats = 64512 B

__global__ __launch_bounds__(128)
void offmask_kernel(const float* __restrict__ omap, const float* __restrict__ mmap,
                    const float* __restrict__ ow,   const float* __restrict__ obias,
                    const float* __restrict__ mw,   const float* __restrict__ mbias)
{
    extern __shared__ float ws[];

    const int tid = threadIdx.x;
    const int b   = blockIdx.x >> 7;
    const int row = blockIdx.x & 127;
    const int wo  = tid;

    // One-time weight stage (scattered reads, L2-cached: 73 KB total)
    for (int i = tid; i < OFF_SMEM_FLOATS; i += 128) {
        int k = i / 1792;
        int r = i % 1792;
        int c = r / 28;
        int t = r % 28;
        float v = 0.f;
        if (t < 18)      v = ow[t * 576 + c * 9 + k];
        else if (t < 27) v = mw[(t - 18) * 576 + c * 9 + k];
        ws[i] = v;
    }
    __syncthreads();

    ull acc[14];
#pragma unroll
    for (int i = 0; i < 14; i++) acc[i] = 0ull;

    const float* ob = omap + (size_t)b * Cc * HW;
    const float* mb = mmap + (size_t)b * Cc * HW;

#pragma unroll 1
    for (int k = 0; k < 9; k++) {
        const int ki = k / 3, kj = k % 3;
        const int py = row - 1 + ki;
        const int px = wo - 1 + kj;
        const bool valid = ((unsigned)py < (unsigned)Hh) & ((unsigned)px < (unsigned)Ww);
        const float* qo = ob + py * Ww + px;
        const float* qm = mb + py * Ww + px;
        const float* wk = &ws[k * 1792];

#pragma unroll 4
        for (int c = 0; c < Cc; c++) {
            float iv = valid ? __ldg(qo + c * HW) : 0.f;
            float mv = valid ? __ldg(qm + c * HW) : 0.f;
            ull ai = pack2(iv, iv);
            ull am = pack2(mv, mv);
            const ulonglong2* wc = (const ulonglong2*)&wk[c * 28];
            ulonglong2 w;
            w = wc[0]; ffma2(acc[0],  ai, w.x); ffma2(acc[1],  ai, w.y);
            w = wc[1]; ffma2(acc[2],  ai, w.x); ffma2(acc[3],  ai, w.y);
            w = wc[2]; ffma2(acc[4],  ai, w.x); ffma2(acc[5],  ai, w.y);
            w = wc[3]; ffma2(acc[6],  ai, w.x); ffma2(acc[7],  ai, w.y);
            w = wc[4]; ffma2(acc[8],  ai, w.x); ffma2(acc[9],  am, w.y);
            w = wc[5]; ffma2(acc[10], am, w.x); ffma2(acc[11], am, w.y);
            w = wc[6]; ffma2(acc[12], am, w.x); ffma2(acc[13], am, w.y);
        }
    }

    float v[28];
#pragma unroll
    for (int i = 0; i < 14; i++) unpack2(acc[i], v[2 * i], v[2 * i + 1]);

    const int p = row * Ww + wo;
    float* S = g_scratch + (size_t)b * 27 * HW;
#pragma unroll
    for (int k = 0; k < 9; k++) {
        S[k * HW + p]       = v[2 * k]     + __ldg(&obias[2 * k]);
        S[(9 + k) * HW + p] = v[2 * k + 1] + __ldg(&obias[2 * k + 1]);
    }
#pragma unroll
    for (int t = 0; t < 9; t++) {
        float z = v[18 + t] + __ldg(&mbias[t]);
        S[(18 + t) * HW + p] = 2.0f / (1.0f + expf(-z));
    }
}

// ---------------------------------------------------------------------------
// Kernel 2: prep2 — NHWC transpose of x (blocks 0..1023) + tf32-split
// interleaved main-GEMM weights (remaining blocks).
// ---------------------------------------------------------------------------
#define NT_BLOCKS 1024           // 4 batches x 256 pixel-tiles of 64
#define WP_TOTAL  (9 * 4096)
#define WP_BLOCKS ((WP_TOTAL + 255) / 256)

__global__ void prep2_kernel(const float* __restrict__ x, const float* __restrict__ w)
{
    if (blockIdx.x < NT_BLOCKS) {
        __shared__ float t[64][65];
        const int b  = blockIdx.x >> 8;
        const int p0 = (blockIdx.x & 255) * 64;
        const float* xb = x + (size_t)b * Cc * HW;
        for (int i = threadIdx.x; i < 4096; i += 256) {
            int c = i >> 6, j = i & 63;
            t[j][c] = __ldg(&xb[c * HW + p0 + j]);
        }
        __syncthreads();
        float* dst = g_xt + (size_t)b * HW * 64 + (size_t)p0 * 64;
        for (int i = threadIdx.x; i < 4096; i += 256)
            dst[i] = t[i >> 6][i & 63];
    } else {
        int i = (blockIdx.x - NT_BLOCKS) * 256 + threadIdx.x;
        if (i < WP_TOTAL) {
            int k = i >> 12;
            int r = i & 4095;
            int o = r >> 6;
            int c = r & 63;
            float v = w[o * 576 + c * 9 + k];
            uint32_t hb = f2tf32(v);
            float hif = __uint_as_float(hb);
            int pos = ((c >> 3) << 3) + ((c & 3) << 1) + ((c >> 2) & 1);
            g_wbh[k * 4096 + o * 64 + pos] = hif;
            g_wbl[k * 4096 + o * 64 + pos] = __uint_as_float(f2tf32(v - hif));
        }
    }
}

// ---------------------------------------------------------------------------
// Kernel 3: deformable conv, warp-level tf32 MMA implicit GEMM (R4 config).
// CTA = 1 image row (M=128 pixels), N=64 outch, K=576. 128 threads.
// Sampling from NHWC g_xt: each corner = 16 x LDG.128 over channels.
// GEMM: 4 warps x 2 m-tiles x 8 n-tiles, 3-product tf32 split,
// B fragments via LDS.64 (interleaved layout).
// ---------------------------------------------------------------------------
#define SA_STRIDE 68
#define SA_HI 0
#define SA_LO (SA_HI + 128 * SA_STRIDE)          // 8704
#define SB_HI (SA_LO + 128 * SA_STRIDE)          // 17408
#define SB_LO (SB_HI + 64 * SA_STRIDE)           // 21760
#define SM_FLOATS (SB_LO + 64 * SA_STRIDE)       // 26112 floats = 104448 B

__global__ __launch_bounds__(128)
void deform_kernel(float* __restrict__ out)
{
    extern __shared__ float smf[];
    uint32_t* smu = (uint32_t*)smf;

    const int tid  = threadIdx.x;
    const int lane = tid & 31;
    const int warp = tid >> 5;
    const int g    = lane >> 2;
    const int tg   = lane & 3;

    const int b   = blockIdx.x >> 7;
    const int row = blockIdx.x & 127;
    const int pix = tid;
    const int p   = row * Ww + pix;

    const float* S  = g_scratch + (size_t)b * 27 * HW;
    const float* xt = g_xt + (size_t)b * HW * 64;

    float acc[2][8][4];
#pragma unroll
    for (int mt = 0; mt < 2; mt++)
#pragma unroll
        for (int nt = 0; nt < 8; nt++)
#pragma unroll
            for (int r = 0; r < 4; r++) acc[mt][nt][r] = 0.f;

#pragma unroll 1
    for (int k = 0; k < 9; k++) {
        __syncthreads();

        // ---- stage B tiles (interleaved layout preserved by raw copy) ----
        {
            const float4* sh = (const float4*)&g_wbh[k * 4096];
            const float4* sl = (const float4*)&g_wbl[k * 4096];
#pragma unroll
            for (int i = tid; i < 1024; i += 128) {
                int o = i >> 4, q = i & 15;
                float4 vh = sh[i];
                float4 vl = sl[i];
                *(float4*)&smf[SB_HI + o * SA_STRIDE + q * 4] = vh;
                *(float4*)&smf[SB_LO + o * SA_STRIDE + q * 4] = vl;
            }
        }

        // ---- tap descriptor ----
        const float dy = S[k * HW + p];
        const float dx = S[(9 + k) * HW + p];
        const float m  = S[(18 + k) * HW + p];
        const float py = dy + (float)(row - 1 + k / 3);
        const float px = dx + (float)(pix - 1 + k % 3);
        const float fy = floorf(py), fx = floorf(px);
        const int y0 = (int)fy, x0 = (int)fx;
        const int y1 = y0 + 1,  x1 = x0 + 1;
        const float wy = py - fy, wx = px - fx;

        const bool vy0 = ((unsigned)y0 < (unsigned)Hh);
        const bool vy1 = ((unsigned)y1 < (unsigned)Hh);
        const bool vx0 = ((unsigned)x0 < (unsigned)Ww);
        const bool vx1 = ((unsigned)x1 < (unsigned)Ww);
        const int y0c = min(max(y0, 0), Hh - 1);
        const int y1c = min(max(y1, 0), Hh - 1);
        const int x0c = min(max(x0, 0), Ww - 1);
        const int x1c = min(max(x1, 0), Ww - 1);

        float c00 = (1.f - wy) * (1.f - wx) * m; c00 = (vy0 & vx0) ? c00 : 0.f;
        float c01 = (1.f - wy) * wx         * m; c01 = (vy0 & vx1) ? c01 : 0.f;
        float c10 = wy * (1.f - wx)         * m; c10 = (vy1 & vx0) ? c10 : 0.f;
        float c11 = wy * wx                 * m; c11 = (vy1 & vx1) ? c11 : 0.f;

        const float4* q00 = (const float4*)(xt + (y0c * Ww + x0c) * 64);
        const float4* q01 = (const float4*)(xt + (y0c * Ww + x1c) * 64);
        const float4* q10 = (const float4*)(xt + (y1c * Ww + x0c) * 64);
        const float4* q11 = (const float4*)(xt + (y1c * Ww + x1c) * 64);

        // ---- sample 64 channels via vector loads, split hi/lo, STS ----
#pragma unroll 4
        for (int cg = 0; cg < 16; cg++) {
            float4 v00 = __ldg(q00 + cg);
            float4 v01 = __ldg(q01 + cg);
            float4 v10 = __ldg(q10 + cg);
            float4 v11 = __ldg(q11 + cg);
            float s0 = fmaf(v11.x, c11, fmaf(v10.x, c10, fmaf(v01.x, c01, v00.x * c00)));
            float s1 = fmaf(v11.y, c11, fmaf(v10.y, c10, fmaf(v01.y, c01, v00.y * c00)));
            float s2 = fmaf(v11.z, c11, fmaf(v10.z, c10, fmaf(v01.z, c01, v00.z * c00)));
            float s3 = fmaf(v11.w, c11, fmaf(v10.w, c10, fmaf(v01.w, c01, v00.w * c00)));
            float h0 = __uint_as_float(f2tf32(s0));
            float h1 = __uint_as_float(f2tf32(s1));
            float h2 = __uint_as_float(f2tf32(s2));
            float h3 = __uint_as_float(f2tf32(s3));
            *(float4*)&smf[SA_HI + pix * SA_STRIDE + cg * 4] =
                make_float4(h0, h1, h2, h3);
            *(float4*)&smf[SA_LO + pix * SA_STRIDE + cg * 4] =
                make_float4(__uint_as_float(f2tf32(s0 - h0)),
                            __uint_as_float(f2tf32(s1 - h1)),
                            __uint_as_float(f2tf32(s2 - h2)),
                            __uint_as_float(f2tf32(s3 - h3)));
        }

        __syncthreads();

        // ---- GEMM: 8 k-steps x (2 m-tiles x 8 n-tiles) x 3 products ----
#pragma unroll
        for (int ks = 0; ks < 8; ks++) {
            uint32_t ah[2][4], al[2][4];
#pragma unroll
            for (int mt = 0; mt < 2; mt++) {
                const int r0 = warp * 32 + mt * 16 + g;
                const int base = r0 * SA_STRIDE + ks * 8 + tg;
                ah[mt][0] = smu[SA_HI + base];
                ah[mt][1] = smu[SA_HI + base + 8 * SA_STRIDE];
                ah[mt][2] = smu[SA_HI + base + 4];
                ah[mt][3] = smu[SA_HI + base + 8 * SA_STRIDE + 4];
                al[mt][0] = smu[SA_LO + base];
                al[mt][1] = smu[SA_LO + base + 8 * SA_STRIDE];
                al[mt][2] = smu[SA_LO + base + 4];
                al[mt][3] = smu[SA_LO + base + 8 * SA_STRIDE + 4];
            }
#pragma unroll
            for (int nt = 0; nt < 8; nt++) {
                const int o  = nt * 8 + g;
                const int bb = o * SA_STRIDE + ks * 8 + tg * 2;
                uint2 bh = *(const uint2*)&smu[SB_HI + bb];
                uint2 bl = *(const uint2*)&smu[SB_LO + bb];
#pragma unroll
                for (int mt = 0; mt < 2; mt++) {
                    MMA_TF32(acc[mt][nt], ah[mt], bh.x, bh.y);
                    MMA_TF32(acc[mt][nt], al[mt], bh.x, bh.y);
                    MMA_TF32(acc[mt][nt], ah[mt], bl.x, bl.y);
                }
            }
        }
    }

    // ---- epilogue: write D fragments to out[b][o][row][x] ----
    float* ob = out + (size_t)b * Oo * HW + row * Ww;
#pragma unroll
    for (int mt = 0; mt < 2; mt++) {
        const int r0 = warp * 32 + mt * 16 + g;
        const int r1 = r0 + 8;
#pragma unroll
        for (int nt = 0; nt < 8; nt++) {
            const int o0 = nt * 8 + tg * 2;
            ob[(o0)     * HW + r0] = acc[mt][nt][0];
            ob[(o0 + 1) * HW + r0] = acc[mt][nt][1];
            ob[(o0)     * HW + r1] = acc[mt][nt][2];
            ob[(o0 + 1) * HW + r1] = acc[mt][nt][3];
        }
    }
}

// ---------------------------------------------------------------------------

extern "C" void kernel_launch(void* const* d_in, const int* in_sizes, int n_in,
                              void* d_out, int out_size)
{
    const float* x     = (const float*)d_in[0];
    const float* omap  = (const float*)d_in[1];
    const float* mmap  = (const float*)d_in[2];
    const float* ow    = (const float*)d_in[3];
    const float* obias = (const float*)d_in[4];
    const float* mw    = (const float*)d_in[5];
    const float* mbias = (const float*)d_in[6];
    const float* w     = (const float*)d_in[7];
    float* out = (float*)d_out;

    dim3 grid(Bb * Hh);    // 512 blocks

    const int off_smem = OFF_SMEM_FLOATS * (int)sizeof(float);   // 64512
    cudaFuncSetAttribute(offmask_kernel, cudaFuncAttributeMaxDynamicSharedMemorySize, off_smem);
    offmask_kernel<<<grid, 128, off_smem>>>(omap, mmap, ow, obias, mw, mbias);

    prep2_kernel<<<NT_BLOCKS + WP_BLOCKS, 256>>>(x, w);

    const int smem_bytes = SM_FLOATS * (int)sizeof(float);       // 104448
    cudaFuncSetAttribute(deform_kernel, cudaFuncAttributeMaxDynamicSharedMemorySize, smem_bytes);
    deform_kernel<<<grid, 128, smem_bytes>>>(out);
}

// round 7
// speedup vs baseline: 2.0559x; 2.0559x over previous
#include <cuda_runtime.h>
#include <math.h>
#include <stdint.h>

#define HW   (128 * 128)
#define Hh   128
#define Ww   128
#define Bb   4
#define Cc   64
#define Oo   64

// Scratch: offsets/mask planes [B][27][H][W]  (0..8 dy_k, 9..17 dx_k, 18..26 mask_k)
__device__ float g_scratch[Bb * 27 * HW];
// Pre-transposed offset+mod weights: [k][c][28]  (0..17 offset-out, 18..26 mod-out, 27 pad)
__device__ float g_wt2[9 * 64 * 28];
// Pre-split tf32 B matrices: [tap][o][pos(c)] interleaved so the (b0,b1) MMA
// fragment pair is one LDS.64:  pos(c) = (c>>3)*8 + (c&3)*2 + ((c>>2)&1)
__device__ float g_wbh[9 * 64 * 64];
__device__ float g_wbl[9 * 64 * 64];

typedef unsigned long long ull;

// ---------------- helpers ----------------
__device__ __forceinline__ uint32_t f2tf32(float s) {
    uint32_t r; asm("cvt.rna.tf32.f32 %0, %1;" : "=r"(r) : "f"(s)); return r;
}
__device__ __forceinline__ void ffma2(ull &acc, ull a, ull b) {
    asm("fma.rn.f32x2 %0, %1, %2, %0;" : "+l"(acc) : "l"(a), "l"(b));
}
__device__ __forceinline__ ull pack2(float x, float y) {
    ull r; asm("mov.b64 %0, {%1, %2};" : "=l"(r) : "f"(x), "f"(y)); return r;
}
__device__ __forceinline__ void unpack2(ull v, float &x, float &y) {
    asm("mov.b64 {%0, %1}, %2;" : "=f"(x), "=f"(y) : "l"(v));
}

#define MMA_TF32(d, a, b0, b1) \
    asm volatile("mma.sync.aligned.m16n8k8.row.col.f32.tf32.tf32.f32 " \
        "{%0,%1,%2,%3}, {%4,%5,%6,%7}, {%8,%9}, {%0,%1,%2,%3};" \
        : "+f"((d)[0]), "+f"((d)[1]), "+f"((d)[2]), "+f"((d)[3]) \
        : "r"((a)[0]), "r"((a)[1]), "r"((a)[2]), "r"((a)[3]), "r"(b0), "r"(b1))

// ---------------------------------------------------------------------------
// Prep: pre-transposed offmask weights + tf32-split interleaved B matrices.
// ---------------------------------------------------------------------------
__global__ void prep_kernel(const float* __restrict__ w,
                            const float* __restrict__ ow,
                            const float* __restrict__ mw)
{
    int i = blockIdx.x * 256 + threadIdx.x;
    if (i < 9 * 4096) {
        int k = i >> 12;      // tap
        int r = i & 4095;
        int o = r >> 6;       // out channel
        int c = r & 63;       // in channel (K index)
        float v = w[o * 576 + c * 9 + k];
        uint32_t hb = f2tf32(v);
        float hif = __uint_as_float(hb);
        int pos = ((c >> 3) << 3) + ((c & 3) << 1) + ((c >> 2) & 1);
        g_wbh[k * 4096 + o * 64 + pos] = hif;
        g_wbl[k * 4096 + o * 64 + pos] = __uint_as_float(f2tf32(v - hif));
    }
    int j = i - 9 * 4096;
    if (j >= 0 && j < 9 * 64 * 28) {
        int k = j / (64 * 28);
        int r = j % (64 * 28);
        int c = r / 28;
        int t = r % 28;
        float v = 0.f;
        if (t < 18)      v = ow[t * 576 + c * 9 + k];
        else if (t < 27) v = mw[(t - 18) * 576 + c * 9 + k];
        g_wt2[j] = v;
    }
}

// ---------------------------------------------------------------------------
// Kernel 1: fused offset-conv (18) + mod-conv (9) + 2*sigmoid.
// R4 structure (7 KB smem, per-tap weight staging, 8 CTAs/SM) + batched
// load/compute: prefetch 8 channels (16 LDG) then 8x14 FFMA2 blocks.
// ---------------------------------------------------------------------------
__global__ __launch_bounds__(128, 8)
void offmask_kernel(const float* __restrict__ omap, const float* __restrict__ mmap,
                    const float* __restrict__ obias, const float* __restrict__ mbias)
{
    __shared__ float ws[64 * 28];

    const int tid = threadIdx.x;
    const int b   = blockIdx.x >> 7;
    const int row = blockIdx.x & 127;
    const int wo  = tid;

    ull acc[14];
#pragma unroll
    for (int i = 0; i < 14; i++) acc[i] = 0ull;

    const float* ob = omap + (size_t)b * Cc * HW;
    const float* mb = mmap + (size_t)b * Cc * HW;

#pragma unroll 1
    for (int k = 0; k < 9; k++) {
        __syncthreads();
        for (int i = tid; i < 64 * 28; i += 128) ws[i] = g_wt2[k * 64 * 28 + i];
        __syncthreads();

        const int ki = k / 3, kj = k % 3;
        const int py = row - 1 + ki;
        const int px = wo - 1 + kj;
        const bool valid = ((unsigned)py < (unsigned)Hh) & ((unsigned)px < (unsigned)Ww);
        const float* qo = ob + py * Ww + px;
        const float* qm = mb + py * Ww + px;

#pragma unroll 1
        for (int c8 = 0; c8 < Cc; c8 += 8) {
            float iv[8], mv[8];
#pragma unroll
            for (int j = 0; j < 8; j++) {
                iv[j] = valid ? __ldg(qo + (c8 + j) * HW) : 0.f;
                mv[j] = valid ? __ldg(qm + (c8 + j) * HW) : 0.f;
            }
#pragma unroll
            for (int j = 0; j < 8; j++) {
                ull ai = pack2(iv[j], iv[j]);
                ull am = pack2(mv[j], mv[j]);
                const ulonglong2* wc = (const ulonglong2*)&ws[(c8 + j) * 28];
                ulonglong2 w;
                w = wc[0]; ffma2(acc[0],  ai, w.x); ffma2(acc[1],  ai, w.y);
                w = wc[1]; ffma2(acc[2],  ai, w.x); ffma2(acc[3],  ai, w.y);
                w = wc[2]; ffma2(acc[4],  ai, w.x); ffma2(acc[5],  ai, w.y);
                w = wc[3]; ffma2(acc[6],  ai, w.x); ffma2(acc[7],  ai, w.y);
                w = wc[4]; ffma2(acc[8],  ai, w.x); ffma2(acc[9],  am, w.y);
                w = wc[5]; ffma2(acc[10], am, w.x); ffma2(acc[11], am, w.y);
                w = wc[6]; ffma2(acc[12], am, w.x); ffma2(acc[13], am, w.y);
            }
        }
    }

    float v[28];
#pragma unroll
    for (int i = 0; i < 14; i++) unpack2(acc[i], v[2 * i], v[2 * i + 1]);

    const int p = row * Ww + wo;
    float* S = g_scratch + (size_t)b * 27 * HW;
#pragma unroll
    for (int k = 0; k < 9; k++) {
        S[k * HW + p]       = v[2 * k]     + __ldg(&obias[2 * k]);
        S[(9 + k) * HW + p] = v[2 * k + 1] + __ldg(&obias[2 * k + 1]);
    }
#pragma unroll
    for (int t = 0; t < 9; t++) {
        float z = v[18 + t] + __ldg(&mbias[t]);
        S[(18 + t) * HW + p] = 2.0f / (1.0f + expf(-z));
    }
}

// ---------------------------------------------------------------------------
// Kernel 2: deformable conv, warp-level tf32 MMA implicit GEMM (R4 config).
// CTA = 1 image row (M=128 pixels), N=64 outch, K=576. 128 threads.
// NCHW scalar gather (adjacent threads = adjacent pixels: coalesced per plane).
// GEMM: 4 warps x 2 m-tiles x 8 n-tiles, 3-product tf32 split,
// B fragments via LDS.64 (interleaved layout).
// ---------------------------------------------------------------------------
#define SA_STRIDE 68
#define SA_HI 0
#define SA_LO (SA_HI + 128 * SA_STRIDE)          // 8704
#define SB_HI (SA_LO + 128 * SA_STRIDE)          // 17408
#define SB_LO (SB_HI + 64 * SA_STRIDE)           // 21760
#define SM_FLOATS (SB_LO + 64 * SA_STRIDE)       // 26112 floats = 104448 B

__global__ __launch_bounds__(128)
void deform_kernel(const float* __restrict__ x, float* __restrict__ out)
{
    extern __shared__ float smf[];
    uint32_t* smu = (uint32_t*)smf;

    const int tid  = threadIdx.x;
    const int lane = tid & 31;
    const int warp = tid >> 5;
    const int g    = lane >> 2;
    const int tg   = lane & 3;

    const int b   = blockIdx.x >> 7;
    const int row = blockIdx.x & 127;
    const int pix = tid;
    const int p   = row * Ww + pix;

    const float* S  = g_scratch + (size_t)b * 27 * HW;
    const float* xb = x + (size_t)b * Cc * HW;

    float acc[2][8][4];
#pragma unroll
    for (int mt = 0; mt < 2; mt++)
#pragma unroll
        for (int nt = 0; nt < 8; nt++)
#pragma unroll
            for (int r = 0; r < 4; r++) acc[mt][nt][r] = 0.f;

#pragma unroll 1
    for (int k = 0; k < 9; k++) {
        __syncthreads();   // previous tap's fragment reads complete

        // ---- stage B tiles (interleaved layout preserved by raw copy) ----
        {
            const float4* sh = (const float4*)&g_wbh[k * 4096];
            const float4* sl = (const float4*)&g_wbl[k * 4096];
#pragma unroll
            for (int i = tid; i < 1024; i += 128) {
                int o = i >> 4, q = i & 15;
                float4 vh = sh[i];
                float4 vl = sl[i];
                *(float4*)&smf[SB_HI + o * SA_STRIDE + q * 4] = vh;
                *(float4*)&smf[SB_LO + o * SA_STRIDE + q * 4] = vl;
            }
        }

        // ---- tap descriptor ----
        const float dy = S[k * HW + p];
        const float dx = S[(9 + k) * HW + p];
        const float m  = S[(18 + k) * HW + p];
        const float py = dy + (float)(row - 1 + k / 3);
        const float px = dx + (float)(pix - 1 + k % 3);
        const float fy = floorf(py), fx = floorf(px);
        const int y0 = (int)fy, x0 = (int)fx;
        const int y1 = y0 + 1,  x1 = x0 + 1;
        const float wy = py - fy, wx = px - fx;

        const bool vy0 = ((unsigned)y0 < (unsigned)Hh);
        const bool vy1 = ((unsigned)y1 < (unsigned)Hh);
        const bool vx0 = ((unsigned)x0 < (unsigned)Ww);
        const bool vx1 = ((unsigned)x1 < (unsigned)Ww);
        const int y0c = min(max(y0, 0), Hh - 1);
        const int y1c = min(max(y1, 0), Hh - 1);
        const int x0c = min(max(x0, 0), Ww - 1);
        const int x1c = min(max(x1, 0), Ww - 1);

        float c00 = (1.f - wy) * (1.f - wx) * m; c00 = (vy0 & vx0) ? c00 : 0.f;
        float c01 = (1.f - wy) * wx         * m; c01 = (vy0 & vx1) ? c01 : 0.f;
        float c10 = wy * (1.f - wx)         * m; c10 = (vy1 & vx0) ? c10 : 0.f;
        float c11 = wy * wx                 * m; c11 = (vy1 & vx1) ? c11 : 0.f;

        const float* q00 = xb + y0c * Ww + x0c;
        const float* q01 = xb + y0c * Ww + x1c;
        const float* q10 = xb + y1c * Ww + x0c;
        const float* q11 = xb + y1c * Ww + x1c;

        // ---- sample 64 channels, split hi/lo, STS into A tiles ----
#pragma unroll 4
        for (int cg = 0; cg < 16; cg++) {
            float hi4[4], lo4[4];
#pragma unroll
            for (int j = 0; j < 4; j++) {
                const int c = cg * 4 + j;
                float s = __ldg(q00 + c * HW) * c00;
                s = fmaf(__ldg(q01 + c * HW), c01, s);
                s = fmaf(__ldg(q10 + c * HW), c10, s);
                s = fmaf(__ldg(q11 + c * HW), c11, s);
                uint32_t hb = f2tf32(s);
                hi4[j] = __uint_as_float(hb);
                lo4[j] = __uint_as_float(f2tf32(s - hi4[j]));
            }
            *(float4*)&smf[SA_HI + pix * SA_STRIDE + cg * 4] =
                make_float4(hi4[0], hi4[1], hi4[2], hi4[3]);
            *(float4*)&smf[SA_LO + pix * SA_STRIDE + cg * 4] =
                make_float4(lo4[0], lo4[1], lo4[2], lo4[3]);
        }

        __syncthreads();

        // ---- GEMM: 8 k-steps x (2 m-tiles x 8 n-tiles) x 3 products ----
#pragma unroll
        for (int ks = 0; ks < 8; ks++) {
            uint32_t ah[2][4], al[2][4];
#pragma unroll
            for (int mt = 0; mt < 2; mt++) {
                const int r0 = warp * 32 + mt * 16 + g;
                const int base = r0 * SA_STRIDE + ks * 8 + tg;
                ah[mt][0] = smu[SA_HI + base];
                ah[mt][1] = smu[SA_HI + base + 8 * SA_STRIDE];
                ah[mt][2] = smu[SA_HI + base + 4];
                ah[mt][3] = smu[SA_HI + base + 8 * SA_STRIDE + 4];
                al[mt][0] = smu[SA_LO + base];
                al[mt][1] = smu[SA_LO + base + 8 * SA_STRIDE];
                al[mt][2] = smu[SA_LO + base + 4];
                al[mt][3] = smu[SA_LO + base + 8 * SA_STRIDE + 4];
            }
#pragma unroll
            for (int nt = 0; nt < 8; nt++) {
                const int o  = nt * 8 + g;
                const int bb = o * SA_STRIDE + ks * 8 + tg * 2;
                uint2 bh = *(const uint2*)&smu[SB_HI + bb];
                uint2 bl = *(const uint2*)&smu[SB_LO + bb];
#pragma unroll
                for (int mt = 0; mt < 2; mt++) {
                    MMA_TF32(acc[mt][nt], ah[mt], bh.x, bh.y);
                    MMA_TF32(acc[mt][nt], al[mt], bh.x, bh.y);
                    MMA_TF32(acc[mt][nt], ah[mt], bl.x, bl.y);
                }
            }
        }
    }

    // ---- epilogue: write D fragments to out[b][o][row][x] ----
    float* ob = out + (size_t)b * Oo * HW + row * Ww;
#pragma unroll
    for (int mt = 0; mt < 2; mt++) {
        const int r0 = warp * 32 + mt * 16 + g;
        const int r1 = r0 + 8;
#pragma unroll
        for (int nt = 0; nt < 8; nt++) {
            const int o0 = nt * 8 + tg * 2;
            ob[(o0)     * HW + r0] = acc[mt][nt][0];
            ob[(o0 + 1) * HW + r0] = acc[mt][nt][1];
            ob[(o0)     * HW + r1] = acc[mt][nt][2];
            ob[(o0 + 1) * HW + r1] = acc[mt][nt][3];
        }
    }
}

// ---------------------------------------------------------------------------

extern "C" void kernel_launch(void* const* d_in, const int* in_sizes, int n_in,
                              void* d_out, int out_size)
{
    const float* x     = (const float*)d_in[0];
    const float* omap  = (const float*)d_in[1];
    const float* mmap  = (const float*)d_in[2];
    const float* ow    = (const float*)d_in[3];
    const float* obias = (const float*)d_in[4];
    const float* mw    = (const float*)d_in[5];
    const float* mbias = (const float*)d_in[6];
    const float* w     = (const float*)d_in[7];
    float* out = (float*)d_out;

    const int prep_total = 9 * 4096 + 9 * 64 * 28;
    prep_kernel<<<(prep_total + 255) / 256, 256>>>(w, ow, mw);

    dim3 grid(Bb * Hh);     // 512 blocks, 1 image row each
    offmask_kernel<<<grid, 128>>>(omap, mmap, obias, mbias);

    const int smem_bytes = SM_FLOATS * (int)sizeof(float);   // 104448
    cudaFuncSetAttribute(deform_kernel, cudaFuncAttributeMaxDynamicSharedMemorySize, smem_bytes);
    deform_kernel<<<grid, 128, smem_bytes>>>(x, out);
}

// round 8
// speedup vs baseline: 2.4444x; 1.1890x over previous
#include <cuda_runtime.h>
#include <cuda_bf16.h>
#include <math.h>
#include <stdint.h>

#define HW   (128 * 128)
#define Hh   128
#define Ww   128
#define Bb   4
#define Cc   64
#define Oo   64

// Scratch: offsets/mask planes [B][27][H][W]  (0..8 dy_k, 9..17 dx_k, 18..26 mask_k)
__device__ float g_scratch[Bb * 27 * HW];
// Pre-transposed offset+mod weights: [k][c][28]  (0..17 offset-out, 18..26 mod-out, 27 pad)
__device__ float g_wt2[9 * 64 * 28];
// Pre-split bf16 B images for main GEMM: exact smem image [tap][64 rows x 40 words]
// word(o, kp): ks=kp>>3, j=kp&7 -> o*40 + ks*8 + 2*((j&3)^((o>>2)&3)) + (j>>2)
__device__ __align__(16) uint32_t g_wbh[9 * 64 * 40];
__device__ __align__(16) uint32_t g_wbl[9 * 64 * 40];

typedef unsigned long long ull;

// ---------------- helpers ----------------
__device__ __forceinline__ void ffma2(ull &acc, ull a, ull b) {
    asm("fma.rn.f32x2 %0, %1, %2, %0;" : "+l"(acc) : "l"(a), "l"(b));
}
__device__ __forceinline__ ull pack2(float x, float y) {
    ull r; asm("mov.b64 %0, {%1, %2};" : "=l"(r) : "f"(x), "f"(y)); return r;
}
__device__ __forceinline__ void unpack2(ull v, float &x, float &y) {
    asm("mov.b64 {%0, %1}, %2;" : "=f"(x), "=f"(y) : "l"(v));
}
// pack two floats as bf16x2 (a -> low half = lower k index)
__device__ __forceinline__ uint32_t bfpack(float a, float b) {
    __nv_bfloat162 t = __floats2bfloat162_rn(a, b);
    return *(uint32_t*)&t;
}
// bf16 split: s = hi + lo (+ 2^-17 residue)
__device__ __forceinline__ void bfsplit(float s, float &hi, float &lo) {
    hi = __bfloat162float(__float2bfloat16(s));
    lo = s - hi;
}

#define MMA_BF16(d, a, b0, b1) \
    asm volatile("mma.sync.aligned.m16n8k16.row.col.f32.bf16.bf16.f32 " \
        "{%0,%1,%2,%3}, {%4,%5,%6,%7}, {%8,%9}, {%0,%1,%2,%3};" \
        : "+f"((d)[0]), "+f"((d)[1]), "+f"((d)[2]), "+f"((d)[3]) \
        : "r"((a)[0]), "r"((a)[1]), "r"((a)[2]), "r"((a)[3]), "r"(b0), "r"(b1))

// ---------------------------------------------------------------------------
// Prep: offmask weight transpose + bf16-split swizzled B images.
// ---------------------------------------------------------------------------
__global__ void prep_kernel(const float* __restrict__ w,
                            const float* __restrict__ ow,
                            const float* __restrict__ mw)
{
    int i = blockIdx.x * 256 + threadIdx.x;
    if (i < 9 * 2048) {           // 9 taps x 64 o x 32 kpairs
        int k  = i >> 11;
        int r  = i & 2047;
        int o  = r >> 5;
        int kp = r & 31;
        int c0 = 2 * kp, c1 = c0 + 1;
        float v0 = w[o * 576 + c0 * 9 + k];
        float v1 = w[o * 576 + c1 * 9 + k];
        float h0, l0, h1, l1;
        bfsplit(v0, h0, l0);
        bfsplit(v1, h1, l1);
        int ks = kp >> 3, j = kp & 7;
        int word = o * 40 + ks * 8 + 2 * ((j & 3) ^ ((o >> 2) & 3)) + (j >> 2);
        g_wbh[k * 2560 + word] = bfpack(h0, h1);
        g_wbl[k * 2560 + word] = bfpack(__bfloat162float(__float2bfloat16(l0)) == 0.f ? l0 : l0,
                                        l1);   // plain bfpack of (l0,l1)
    }
    int j = i - 9 * 2048;
    if (j >= 0 && j < 9 * 64 * 28) {
        int k = j / (64 * 28);
        int r = j % (64 * 28);
        int c = r / 28;
        int t = r % 28;
        float v = 0.f;
        if (t < 18)      v = ow[t * 576 + c * 9 + k];
        else if (t < 27) v = mw[(t - 18) * 576 + c * 9 + k];
        g_wt2[j] = v;
    }
}

// ---------------------------------------------------------------------------
// Kernel 1: fused offset-conv (18) + mod-conv (9) + 2*sigmoid. (R7 form)
// ---------------------------------------------------------------------------
__global__ __launch_bounds__(128, 8)
void offmask_kernel(const float* __restrict__ omap, const float* __restrict__ mmap,
                    const float* __restrict__ obias, const float* __restrict__ mbias)
{
    __shared__ float ws[64 * 28];

    const int tid = threadIdx.x;
    const int b   = blockIdx.x >> 7;
    const int row = blockIdx.x & 127;
    const int wo  = tid;

    ull acc[14];
#pragma unroll
    for (int i = 0; i < 14; i++) acc[i] = 0ull;

    const float* ob = omap + (size_t)b * Cc * HW;
    const float* mb = mmap + (size_t)b * Cc * HW;

#pragma unroll 1
    for (int k = 0; k < 9; k++) {
        __syncthreads();
        for (int i = tid; i < 64 * 28; i += 128) ws[i] = g_wt2[k * 64 * 28 + i];
        __syncthreads();

        const int ki = k / 3, kj = k % 3;
        const int py = row - 1 + ki;
        const int px = wo - 1 + kj;
        const bool valid = ((unsigned)py < (unsigned)Hh) & ((unsigned)px < (unsigned)Ww);
        const float* qo = ob + py * Ww + px;
        const float* qm = mb + py * Ww + px;

#pragma unroll 1
        for (int c8 = 0; c8 < Cc; c8 += 8) {
            float iv[8], mv[8];
#pragma unroll
            for (int j = 0; j < 8; j++) {
                iv[j] = valid ? __ldg(qo + (c8 + j) * HW) : 0.f;
                mv[j] = valid ? __ldg(qm + (c8 + j) * HW) : 0.f;
            }
#pragma unroll
            for (int j = 0; j < 8; j++) {
                ull ai = pack2(iv[j], iv[j]);
                ull am = pack2(mv[j], mv[j]);
                const ulonglong2* wc = (const ulonglong2*)&ws[(c8 + j) * 28];
                ulonglong2 w;
                w = wc[0]; ffma2(acc[0],  ai, w.x); ffma2(acc[1],  ai, w.y);
                w = wc[1]; ffma2(acc[2],  ai, w.x); ffma2(acc[3],  ai, w.y);
                w = wc[2]; ffma2(acc[4],  ai, w.x); ffma2(acc[5],  ai, w.y);
                w = wc[3]; ffma2(acc[6],  ai, w.x); ffma2(acc[7],  ai, w.y);
                w = wc[4]; ffma2(acc[8],  ai, w.x); ffma2(acc[9],  am, w.y);
                w = wc[5]; ffma2(acc[10], am, w.x); ffma2(acc[11], am, w.y);
                w = wc[6]; ffma2(acc[12], am, w.x); ffma2(acc[13], am, w.y);
            }
        }
    }

    float v[28];
#pragma unroll
    for (int i = 0; i < 14; i++) unpack2(acc[i], v[2 * i], v[2 * i + 1]);

    const int p = row * Ww + wo;
    float* S = g_scratch + (size_t)b * 27 * HW;
#pragma unroll
    for (int k = 0; k < 9; k++) {
        S[k * HW + p]       = v[2 * k]     + __ldg(&obias[2 * k]);
        S[(9 + k) * HW + p] = v[2 * k + 1] + __ldg(&obias[2 * k + 1]);
    }
#pragma unroll
    for (int t = 0; t < 9; t++) {
        float z = v[18 + t] + __ldg(&mbias[t]);
        S[(18 + t) * HW + p] = 2.0f / (1.0f + expf(-z));
    }
}

// ---------------------------------------------------------------------------
// Kernel 2: deformable conv, warp-level bf16 MMA implicit GEMM.
// CTA = 1 image row (M=128 pixels), N=64 outch, K=576. 128 threads.
// A/B in smem as packed bf16x2 words, stride-40 rows + XOR swizzle on the
// 64-bit unit index (u ^= (row>>2)&3) -> conflict-free STS.64 and LDS.64.
// GEMM: 4 warps x 2 m-tiles x 8 n-tiles x 4 k-steps x 3 split products
// of mma.sync.m16n8k16.bf16.  60 KB smem -> 3 CTAs/SM.
// ---------------------------------------------------------------------------
#define ROWW 40
#define SA_HI 0                              // 128*40 = 5120 words
#define SA_LO (SA_HI + 128 * ROWW)           // 5120
#define SB_HI (SA_LO + 128 * ROWW)           // 10240 (64*40 = 2560 words)
#define SB_LO (SB_HI + 64 * ROWW)            // 12800
#define SM_WORDS (SB_LO + 64 * ROWW)         // 15360 words = 61440 B

__global__ __launch_bounds__(128)
void deform_kernel(const float* __restrict__ x, float* __restrict__ out)
{
    extern __shared__ uint32_t smu[];

    const int tid  = threadIdx.x;
    const int lane = tid & 31;
    const int warp = tid >> 5;
    const int g    = lane >> 2;
    const int tg   = lane & 3;

    const int b   = blockIdx.x >> 7;
    const int row = blockIdx.x & 127;
    const int pix = tid;
    const int p   = row * Ww + pix;
    const int swzp = (pix >> 2) & 3;

    const float* S  = g_scratch + (size_t)b * 27 * HW;
    const float* xb = x + (size_t)b * Cc * HW;

    float acc[2][8][4];
#pragma unroll
    for (int mt = 0; mt < 2; mt++)
#pragma unroll
        for (int nt = 0; nt < 8; nt++)
#pragma unroll
            for (int r = 0; r < 4; r++) acc[mt][nt][r] = 0.f;

#pragma unroll 1
    for (int k = 0; k < 9; k++) {
        __syncthreads();   // previous tap's fragment reads complete

        // ---- stage B images (raw copy; swizzle pre-baked by prep) ----
        {
            const uint4* sh = (const uint4*)&g_wbh[k * 2560];
            const uint4* sl = (const uint4*)&g_wbl[k * 2560];
            uint4* dh = (uint4*)&smu[SB_HI];
            uint4* dl = (uint4*)&smu[SB_LO];
#pragma unroll
            for (int i = tid; i < 640; i += 128) {
                dh[i] = sh[i];
                dl[i] = sl[i];
            }
        }

        // ---- tap descriptor ----
        const float dy = S[k * HW + p];
        const float dx = S[(9 + k) * HW + p];
        const float m  = S[(18 + k) * HW + p];
        const float py = dy + (float)(row - 1 + k / 3);
        const float px = dx + (float)(pix - 1 + k % 3);
        const float fy = floorf(py), fx = floorf(px);
        const int y0 = (int)fy, x0 = (int)fx;
        const int y1 = y0 + 1,  x1 = x0 + 1;
        const float wy = py - fy, wx = px - fx;

        const bool vy0 = ((unsigned)y0 < (unsigned)Hh);
        const bool vy1 = ((unsigned)y1 < (unsigned)Hh);
        const bool vx0 = ((unsigned)x0 < (unsigned)Ww);
        const bool vx1 = ((unsigned)x1 < (unsigned)Ww);
        const int y0c = min(max(y0, 0), Hh - 1);
        const int y1c = min(max(y1, 0), Hh - 1);
        const int x0c = min(max(x0, 0), Ww - 1);
        const int x1c = min(max(x1, 0), Ww - 1);

        float c00 = (1.f - wy) * (1.f - wx) * m; c00 = (vy0 & vx0) ? c00 : 0.f;
        float c01 = (1.f - wy) * wx         * m; c01 = (vy0 & vx1) ? c01 : 0.f;
        float c10 = wy * (1.f - wx)         * m; c10 = (vy1 & vx0) ? c10 : 0.f;
        float c11 = wy * wx                 * m; c11 = (vy1 & vx1) ? c11 : 0.f;

        const float* q00 = xb + y0c * Ww + x0c;
        const float* q01 = xb + y0c * Ww + x1c;
        const float* q10 = xb + y1c * Ww + x0c;
        const float* q11 = xb + y1c * Ww + x1c;

        // ---- sample 64 channels, bf16 split, STS.64 pairs ----
#pragma unroll
        for (int ks = 0; ks < 4; ks++) {
#pragma unroll
            for (int kp0 = 0; kp0 < 4; kp0++) {
                const int cA = 16 * ks + 2 * kp0;   // kpA channels cA, cA+1
                const int cB = cA + 8;              // kpB channels cB, cB+1
                float s[4];
                const int cs[4] = { cA, cA + 1, cB, cB + 1 };
#pragma unroll
                for (int j = 0; j < 4; j++) {
                    const int c = cs[j];
                    float v = __ldg(q00 + c * HW) * c00;
                    v = fmaf(__ldg(q01 + c * HW), c01, v);
                    v = fmaf(__ldg(q10 + c * HW), c10, v);
                    v = fmaf(__ldg(q11 + c * HW), c11, v);
                    s[j] = v;
                }
                float h0, l0, h1, l1, h2, l2, h3, l3;
                bfsplit(s[0], h0, l0); bfsplit(s[1], h1, l1);
                bfsplit(s[2], h2, l2); bfsplit(s[3], h3, l3);
                const int wbase = pix * ROWW + ks * 8 + 2 * (kp0 ^ swzp);
                *(uint2*)&smu[SA_HI + wbase] = make_uint2(bfpack(h0, h1), bfpack(h2, h3));
                *(uint2*)&smu[SA_LO + wbase] = make_uint2(bfpack(l0, l1), bfpack(l2, l3));
            }
        }

        __syncthreads();

        // ---- GEMM: 4 k-steps x (2 m-tiles x 8 n-tiles) x 3 products ----
#pragma unroll
        for (int ks = 0; ks < 4; ks++) {
            uint32_t ah[2][4], al[2][4];
#pragma unroll
            for (int mt = 0; mt < 2; mt++) {
                const int r0 = warp * 32 + mt * 16 + g;
                const int r1 = r0 + 8;
                const int w0 = r0 * ROWW + ks * 8 + 2 * (tg ^ ((r0 >> 2) & 3));
                const int w1 = r1 * ROWW + ks * 8 + 2 * (tg ^ ((r1 >> 2) & 3));
                uint2 H0 = *(const uint2*)&smu[SA_HI + w0];
                uint2 H1 = *(const uint2*)&smu[SA_HI + w1];
                uint2 L0 = *(const uint2*)&smu[SA_LO + w0];
                uint2 L1 = *(const uint2*)&smu[SA_LO + w1];
                ah[mt][0] = H0.x; ah[mt][1] = H1.x; ah[mt][2] = H0.y; ah[mt][3] = H1.y;
                al[mt][0] = L0.x; al[mt][1] = L1.x; al[mt][2] = L0.y; al[mt][3] = L1.y;
            }
#pragma unroll
            for (int nt = 0; nt < 8; nt++) {
                const int o  = nt * 8 + g;
                const int wb = o * ROWW + ks * 8 + 2 * (tg ^ ((o >> 2) & 3));
                uint2 bh = *(const uint2*)&smu[SB_HI + wb];
                uint2 bl = *(const uint2*)&smu[SB_LO + wb];
#pragma unroll
                for (int mt = 0; mt < 2; mt++) {
                    MMA_BF16(acc[mt][nt], ah[mt], bh.x, bh.y);
                    MMA_BF16(acc[mt][nt], al[mt], bh.x, bh.y);
                    MMA_BF16(acc[mt][nt], ah[mt], bl.x, bl.y);
                }
            }
        }
    }

    // ---- epilogue: write D fragments to out[b][o][row][x] ----
    float* ob = out + (size_t)b * Oo * HW + row * Ww;
#pragma unroll
    for (int mt = 0; mt < 2; mt++) {
        const int r0 = warp * 32 + mt * 16 + g;
        const int r1 = r0 + 8;
#pragma unroll
        for (int nt = 0; nt < 8; nt++) {
            const int o0 = nt * 8 + tg * 2;
            ob[(o0)     * HW + r0] = acc[mt][nt][0];
            ob[(o0 + 1) * HW + r0] = acc[mt][nt][1];
            ob[(o0)     * HW + r1] = acc[mt][nt][2];
            ob[(o0 + 1) * HW + r1] = acc[mt][nt][3];
        }
    }
}

// ---------------------------------------------------------------------------

extern "C" void kernel_launch(void* const* d_in, const int* in_sizes, int n_in,
                              void* d_out, int out_size)
{
    const float* x     = (const float*)d_in[0];
    const float* omap  = (const float*)d_in[1];
    const float* mmap  = (const float*)d_in[2];
    const float* ow    = (const float*)d_in[3];
    const float* obias = (const float*)d_in[4];
    const float* mw    = (const float*)d_in[5];
    const float* mbias = (const float*)d_in[6];
    const float* w     = (const float*)d_in[7];
    float* out = (float*)d_out;

    const int prep_total = 9 * 2048 + 9 * 64 * 28;   // 18432 + 16128
    prep_kernel<<<(prep_total + 255) / 256, 256>>>(w, ow, mw);

    dim3 grid(Bb * Hh);     // 512 blocks, 1 image row each
    offmask_kernel<<<grid, 128>>>(omap, mmap, obias, mbias);

    const int smem_bytes = SM_WORDS * (int)sizeof(uint32_t);   // 61440
    cudaFuncSetAttribute(deform_kernel, cudaFuncAttributeMaxDynamicSharedMemorySize, smem_bytes);
    deform_kernel<<<grid, 128, smem_bytes>>>(x, out);
}

// round 10
// speedup vs baseline: 2.6373x; 1.0789x over previous
#include <cuda_runtime.h>
#include <cuda_bf16.h>
#include <math.h>
#include <stdint.h>

#define HW   (128 * 128)
#define Hh   128
#define Ww   128
#define Bb   4
#define Cc   64
#define Oo   64

// Scratch: offsets/mask planes [B][27][H][W]  (0..8 dy_k, 9..17 dx_k, 18..26 mask_k)
__device__ float g_scratch[Bb * 27 * HW];
// Pre-split bf16 B images, exact smem layout. word(o,kp) within a tap image:
//   ks=kp>>3, j=kp&7 -> o*40 + ks*8 + 2*((j&3)^((o>>2)&3)) + (j>>2)
__device__ __align__(16) uint32_t g_wbh[9 * 64 * 40];    // deform weight hi
__device__ __align__(16) uint32_t g_wbl[9 * 64 * 40];    // deform weight lo
__device__ __align__(16) uint32_t g_wboh[9 * 24 * 40];   // offset-conv weight hi (rows 18..23 = 0)
__device__ __align__(16) uint32_t g_wbol[9 * 24 * 40];
__device__ __align__(16) uint32_t g_wbmh[9 * 16 * 40];   // mod-conv weight hi (rows 9..15 = 0)
__device__ __align__(16) uint32_t g_wbml[9 * 16 * 40];

// ---------------- helpers ----------------
__device__ __forceinline__ uint32_t bfpack(float a, float b) {
    __nv_bfloat162 t = __floats2bfloat162_rn(a, b);
    return *(uint32_t*)&t;
}
__device__ __forceinline__ void bfsplit(float s, float &hi, float &lo) {
    hi = __bfloat162float(__float2bfloat16(s));
    lo = s - hi;
}

#define MMA_BF16(d, a, b0, b1) \
    asm volatile("mma.sync.aligned.m16n8k16.row.col.f32.bf16.bf16.f32 " \
        "{%0,%1,%2,%3}, {%4,%5,%6,%7}, {%8,%9}, {%0,%1,%2,%3};" \
        : "+f"((d)[0]), "+f"((d)[1]), "+f"((d)[2]), "+f"((d)[3]) \
        : "r"((a)[0]), "r"((a)[1]), "r"((a)[2]), "r"((a)[3]), "r"(b0), "r"(b1))

__device__ __forceinline__ int swz_word(int o, int kp) {
    int ks = kp >> 3, j = kp & 7;
    return o * 40 + ks * 8 + 2 * ((j & 3) ^ ((o >> 2) & 3)) + (j >> 2);
}

// ---------------------------------------------------------------------------
// Prep: bake all bf16-split swizzled B images.
// ---------------------------------------------------------------------------
__global__ void prep_kernel(const float* __restrict__ w,
                            const float* __restrict__ ow,
                            const float* __restrict__ mw)
{
    int i = blockIdx.x * 256 + threadIdx.x;
    if (i < 9 * 2048) {                 // deform: 9 x 64 o x 32 kp
        int k  = i >> 11;
        int r  = i & 2047;
        int o  = r >> 5;
        int kp = r & 31;
        int c0 = 2 * kp;
        float v0 = w[o * 576 + c0 * 9 + k];
        float v1 = w[o * 576 + (c0 + 1) * 9 + k];
        float h0, l0, h1, l1;
        bfsplit(v0, h0, l0); bfsplit(v1, h1, l1);
        int word = swz_word(o, kp);
        g_wbh[k * 2560 + word] = bfpack(h0, h1);
        g_wbl[k * 2560 + word] = bfpack(l0, l1);
    }
    int j = i - 9 * 2048;
    if (j >= 0 && j < 9 * 768) {        // offset conv: 9 x 24 o x 32 kp
        int k  = j / 768;
        int r  = j % 768;
        int o  = r >> 5;
        int kp = r & 31;
        int c0 = 2 * kp;
        float v0 = (o < 18) ? ow[o * 576 + c0 * 9 + k] : 0.f;
        float v1 = (o < 18) ? ow[o * 576 + (c0 + 1) * 9 + k] : 0.f;
        float h0, l0, h1, l1;
        bfsplit(v0, h0, l0); bfsplit(v1, h1, l1);
        int word = swz_word(o, kp);
        g_wboh[k * 960 + word] = bfpack(h0, h1);
        g_wbol[k * 960 + word] = bfpack(l0, l1);
    }
    int l = j - 9 * 768;
    if (l >= 0 && l < 9 * 512) {        // mod conv: 9 x 16 o x 32 kp
        int k  = l / 512;
        int r  = l % 512;
        int o  = r >> 5;
        int kp = r & 31;
        int c0 = 2 * kp;
        float v0 = (o < 9) ? mw[o * 576 + c0 * 9 + k] : 0.f;
        float v1 = (o < 9) ? mw[o * 576 + (c0 + 1) * 9 + k] : 0.f;
        float h0, l0, h1, l1;
        bfsplit(v0, h0, l0); bfsplit(v1, h1, l1);
        int word = swz_word(o, kp);
        g_wbmh[k * 640 + word] = bfpack(h0, h1);
        g_wbml[k * 640 + word] = bfpack(l0, l1);
    }
}

// ---------------------------------------------------------------------------
// Kernel 1: offset+mod convs as warp-level bf16 MMA implicit GEMM.
// CTA = 1 image row. Per tap: stage shifted omap/mmap windows into 4 A tiles
// (hi/lo for each map), then two GEMMs:
//   D1[128 x 24] (offset outputs, 18 real)  and  D2[128 x 16] (mod, 9 real),
// both with the 3-product bf16 split. Epilogue: bias (+2*sigmoid for mod)
// and write to the scratch planes deform consumes.
// ---------------------------------------------------------------------------
#define ROWW 40
#define AO_HI 0
#define AO_LO (AO_HI + 128 * ROWW)      //  5120
#define AM_HI (AO_LO + 128 * ROWW)      // 10240
#define AM_LO (AM_HI + 128 * ROWW)      // 15360
#define BO_HI (AM_LO + 128 * ROWW)      // 20480 (24*40 = 960)
#define BO_LO (BO_HI + 24 * ROWW)       // 21440
#define BM_HI (BO_LO + 24 * ROWW)       // 22400 (16*40 = 640)
#define BM_LO (BM_HI + 16 * ROWW)       // 23040
#define OM_WORDS (BM_LO + 16 * ROWW)    // 23680 words = 94720 B

__global__ __launch_bounds__(128)
void offmask_kernel(const float* __restrict__ omap, const float* __restrict__ mmap,
                    const float* __restrict__ obias, const float* __restrict__ mbias)
{
    extern __shared__ uint32_t smu[];

    const int tid  = threadIdx.x;
    const int lane = tid & 31;
    const int warp = tid >> 5;
    const int g    = lane >> 2;
    const int tg   = lane & 3;

    const int b    = blockIdx.x >> 7;
    const int row  = blockIdx.x & 127;
    const int pix  = tid;
    const int swzp = (pix >> 2) & 3;

    const float* ob = omap + (size_t)b * Cc * HW;
    const float* mb = mmap + (size_t)b * Cc * HW;

    float d1[2][3][4];    // offset GEMM accumulators
    float d2[2][2][4];    // mod GEMM accumulators
#pragma unroll
    for (int mt = 0; mt < 2; mt++) {
#pragma unroll
        for (int nt = 0; nt < 3; nt++)
#pragma unroll
            for (int r = 0; r < 4; r++) d1[mt][nt][r] = 0.f;
#pragma unroll
        for (int nt = 0; nt < 2; nt++)
#pragma unroll
            for (int r = 0; r < 4; r++) d2[mt][nt][r] = 0.f;
    }

#pragma unroll 1
    for (int k = 0; k < 9; k++) {
        __syncthreads();   // previous tap's fragment reads complete

        // ---- stage B images for this tap ----
        {
            const uint4* soh = (const uint4*)&g_wboh[k * 960];
            const uint4* sol = (const uint4*)&g_wbol[k * 960];
            const uint4* smh = (const uint4*)&g_wbmh[k * 640];
            const uint4* sml = (const uint4*)&g_wbml[k * 640];
#pragma unroll
            for (int i = tid; i < 240; i += 128) {
                ((uint4*)&smu[BO_HI])[i] = soh[i];
                ((uint4*)&smu[BO_LO])[i] = sol[i];
            }
#pragma unroll
            for (int i = tid; i < 160; i += 128) {
                ((uint4*)&smu[BM_HI])[i] = smh[i];
                ((uint4*)&smu[BM_LO])[i] = sml[i];
            }
        }

        // ---- load shifted windows, split, STS into A tiles ----
        const int ki = k / 3, kj = k % 3;
        const int py = row - 1 + ki;
        const int px = pix - 1 + kj;
        const bool valid = ((unsigned)py < (unsigned)Hh) & ((unsigned)px < (unsigned)Ww);
        const float* qo = ob + py * Ww + px;
        const float* qm = mb + py * Ww + px;

#pragma unroll
        for (int ks = 0; ks < 4; ks++) {
#pragma unroll
            for (int kp0 = 0; kp0 < 4; kp0++) {
                const int cA = 16 * ks + 2 * kp0;
                const int cs[4] = { cA, cA + 1, cA + 8, cA + 9 };
                float so[4], sm[4];
#pragma unroll
                for (int j = 0; j < 4; j++) {
                    so[j] = valid ? __ldg(qo + cs[j] * HW) : 0.f;
                    sm[j] = valid ? __ldg(qm + cs[j] * HW) : 0.f;
                }
                float oh[4], ol[4], mh[4], ml[4];
#pragma unroll
                for (int j = 0; j < 4; j++) {
                    bfsplit(so[j], oh[j], ol[j]);
                    bfsplit(sm[j], mh[j], ml[j]);
                }
                const int wbase = pix * ROWW + ks * 8 + 2 * (kp0 ^ swzp);
                *(uint2*)&smu[AO_HI + wbase] = make_uint2(bfpack(oh[0], oh[1]), bfpack(oh[2], oh[3]));
                *(uint2*)&smu[AO_LO + wbase] = make_uint2(bfpack(ol[0], ol[1]), bfpack(ol[2], ol[3]));
                *(uint2*)&smu[AM_HI + wbase] = make_uint2(bfpack(mh[0], mh[1]), bfpack(mh[2], mh[3]));
                *(uint2*)&smu[AM_LO + wbase] = make_uint2(bfpack(ml[0], ml[1]), bfpack(ml[2], ml[3]));
            }
        }

        __syncthreads();

        // ---- GEMMs ----
#pragma unroll
        for (int ks = 0; ks < 4; ks++) {
            const int r0 = warp * 32 + g;
            const int r1 = r0 + 8;
            const int r2 = r0 + 16;
            const int r3 = r0 + 24;
            const int w0 = r0 * ROWW + ks * 8 + 2 * (tg ^ ((r0 >> 2) & 3));
            const int w1 = r1 * ROWW + ks * 8 + 2 * (tg ^ ((r1 >> 2) & 3));
            const int w2 = r2 * ROWW + ks * 8 + 2 * (tg ^ ((r2 >> 2) & 3));
            const int w3 = r3 * ROWW + ks * 8 + 2 * (tg ^ ((r3 >> 2) & 3));

            uint32_t aoh[2][4], aol[2][4], amh[2][4], aml[2][4];
            {
                uint2 H0 = *(const uint2*)&smu[AO_HI + w0];
                uint2 H1 = *(const uint2*)&smu[AO_HI + w1];
                uint2 H2 = *(const uint2*)&smu[AO_HI + w2];
                uint2 H3 = *(const uint2*)&smu[AO_HI + w3];
                aoh[0][0] = H0.x; aoh[0][1] = H1.x; aoh[0][2] = H0.y; aoh[0][3] = H1.y;
                aoh[1][0] = H2.x; aoh[1][1] = H3.x; aoh[1][2] = H2.y; aoh[1][3] = H3.y;
                uint2 L0 = *(const uint2*)&smu[AO_LO + w0];
                uint2 L1 = *(const uint2*)&smu[AO_LO + w1];
                uint2 L2 = *(const uint2*)&smu[AO_LO + w2];
                uint2 L3 = *(const uint2*)&smu[AO_LO + w3];
                aol[0][0] = L0.x; aol[0][1] = L1.x; aol[0][2] = L0.y; aol[0][3] = L1.y;
                aol[1][0] = L2.x; aol[1][1] = L3.x; aol[1][2] = L2.y; aol[1][3] = L3.y;
                uint2 M0 = *(const uint2*)&smu[AM_HI + w0];
                uint2 M1 = *(const uint2*)&smu[AM_HI + w1];
                uint2 M2 = *(const uint2*)&smu[AM_HI + w2];
                uint2 M3 = *(const uint2*)&smu[AM_HI + w3];
                amh[0][0] = M0.x; amh[0][1] = M1.x; amh[0][2] = M0.y; amh[0][3] = M1.y;
                amh[1][0] = M2.x; amh[1][1] = M3.x; amh[1][2] = M2.y; amh[1][3] = M3.y;
                uint2 N0 = *(const uint2*)&smu[AM_LO + w0];
                uint2 N1 = *(const uint2*)&smu[AM_LO + w1];
                uint2 N2 = *(const uint2*)&smu[AM_LO + w2];
                uint2 N3 = *(const uint2*)&smu[AM_LO + w3];
                aml[0][0] = N0.x; aml[0][1] = N1.x; aml[0][2] = N0.y; aml[0][3] = N1.y;
                aml[1][0] = N2.x; aml[1][1] = N3.x; aml[1][2] = N2.y; aml[1][3] = N3.y;
            }
#pragma unroll
            for (int nt = 0; nt < 3; nt++) {
                const int o  = nt * 8 + g;
                const int wb = o * ROWW + ks * 8 + 2 * (tg ^ ((o >> 2) & 3));
                uint2 bh = *(const uint2*)&smu[BO_HI + wb];
                uint2 bl = *(const uint2*)&smu[BO_LO + wb];
#pragma unroll
                for (int mt = 0; mt < 2; mt++) {
                    MMA_BF16(d1[mt][nt], aoh[mt], bh.x, bh.y);
                    MMA_BF16(d1[mt][nt], aol[mt], bh.x, bh.y);
                    MMA_BF16(d1[mt][nt], aoh[mt], bl.x, bl.y);
                }
            }
#pragma unroll
            for (int nt = 0; nt < 2; nt++) {
                const int o  = nt * 8 + g;
                const int wb = o * ROWW + ks * 8 + 2 * (tg ^ ((o >> 2) & 3));
                uint2 bh = *(const uint2*)&smu[BM_HI + wb];
                uint2 bl = *(const uint2*)&smu[BM_LO + wb];
#pragma unroll
                for (int mt = 0; mt < 2; mt++) {
                    MMA_BF16(d2[mt][nt], amh[mt], bh.x, bh.y);
                    MMA_BF16(d2[mt][nt], aml[mt], bh.x, bh.y);
                    MMA_BF16(d2[mt][nt], amh[mt], bl.x, bl.y);
                }
            }
        }
    }

    // ---- epilogue: fragments -> scratch planes (bias, 2*sigmoid) ----
    float* S = g_scratch + (size_t)b * 27 * HW + row * Ww;
#pragma unroll
    for (int mt = 0; mt < 2; mt++) {
        const int r0 = warp * 32 + mt * 16 + g;
        const int r1 = r0 + 8;
#pragma unroll
        for (int nt = 0; nt < 3; nt++) {
            const int t0 = nt * 8 + tg * 2;
#pragma unroll
            for (int e = 0; e < 2; e++) {
                const int t = t0 + e;
                if (t < 18) {
                    const int plane = (t & 1) ? (9 + (t >> 1)) : (t >> 1);
                    const float bias = __ldg(&obias[t]);
                    S[plane * HW + r0] = d1[mt][nt][e]     + bias;
                    S[plane * HW + r1] = d1[mt][nt][e + 2] + bias;
                }
            }
        }
#pragma unroll
        for (int nt = 0; nt < 2; nt++) {
            const int t0 = nt * 8 + tg * 2;
#pragma unroll
            for (int e = 0; e < 2; e++) {
                const int t = t0 + e;
                if (t < 9) {
                    const float bias = __ldg(&mbias[t]);
                    float z0 = d2[mt][nt][e]     + bias;
                    float z1 = d2[mt][nt][e + 2] + bias;
                    S[(18 + t) * HW + r0] = 2.0f / (1.0f + expf(-z0));
                    S[(18 + t) * HW + r1] = 2.0f / (1.0f + expf(-z1));
                }
            }
        }
    }
}

// ---------------------------------------------------------------------------
// Kernel 2: deformable conv, warp-level bf16 MMA implicit GEMM (R8, unchanged).
// ---------------------------------------------------------------------------
#define SA_HI 0
#define SA_LO (SA_HI + 128 * ROWW)
#define SB_HI (SA_LO + 128 * ROWW)
#define SB_LO (SB_HI + 64 * ROWW)
#define SM_WORDS (SB_LO + 64 * ROWW)     // 15360 words = 61440 B

__global__ __launch_bounds__(128)
void deform_kernel(const float* __restrict__ x, float* __restrict__ out)
{
    extern __shared__ uint32_t smu[];

    const int tid  = threadIdx.x;
    const int lane = tid & 31;
    const int warp = tid >> 5;
    const int g    = lane >> 2;
    const int tg   = lane & 3;

    const int b   = blockIdx.x >> 7;
    const int row = blockIdx.x & 127;
    const int pix = tid;
    const int p   = row * Ww + pix;
    const int swzp = (pix >> 2) & 3;

    const float* S  = g_scratch + (size_t)b * 27 * HW;
    const float* xb = x + (size_t)b * Cc * HW;

    float acc[2][8][4];
#pragma unroll
    for (int mt = 0; mt < 2; mt++)
#pragma unroll
        for (int nt = 0; nt < 8; nt++)
#pragma unroll
            for (int r = 0; r < 4; r++) acc[mt][nt][r] = 0.f;

#pragma unroll 1
    for (int k = 0; k < 9; k++) {
        __syncthreads();

        {
            const uint4* sh = (const uint4*)&g_wbh[k * 2560];
            const uint4* sl = (const uint4*)&g_wbl[k * 2560];
            uint4* dh = (uint4*)&smu[SB_HI];
            uint4* dl = (uint4*)&smu[SB_LO];
#pragma unroll
            for (int i = tid; i < 640; i += 128) {
                dh[i] = sh[i];
                dl[i] = sl[i];
            }
        }

        const float dy = S[k * HW + p];
        const float dx = S[(9 + k) * HW + p];
        const float m  = S[(18 + k) * HW + p];
        const float py = dy + (float)(row - 1 + k / 3);
        const float px = dx + (float)(pix - 1 + k % 3);
        const float fy = floorf(py), fx = floorf(px);
        const int y0 = (int)fy, x0 = (int)fx;
        const int y1 = y0 + 1,  x1 = x0 + 1;
        const float wy = py - fy, wx = px - fx;

        const bool vy0 = ((unsigned)y0 < (unsigned)Hh);
        const bool vy1 = ((unsigned)y1 < (unsigned)Hh);
        const bool vx0 = ((unsigned)x0 < (unsigned)Ww);
        const bool vx1 = ((unsigned)x1 < (unsigned)Ww);
        const int y0c = min(max(y0, 0), Hh - 1);
        const int y1c = min(max(y1, 0), Hh - 1);
        const int x0c = min(max(x0, 0), Ww - 1);
        const int x1c = min(max(x1, 0), Ww - 1);

        float c00 = (1.f - wy) * (1.f - wx) * m; c00 = (vy0 & vx0) ? c00 : 0.f;
        float c01 = (1.f - wy) * wx         * m; c01 = (vy0 & vx1) ? c01 : 0.f;
        float c10 = wy * (1.f - wx)         * m; c10 = (vy1 & vx0) ? c10 : 0.f;
        float c11 = wy * wx                 * m; c11 = (vy1 & vx1) ? c11 : 0.f;

        const float* q00 = xb + y0c * Ww + x0c;
        const float* q01 = xb + y0c * Ww + x1c;
        const float* q10 = xb + y1c * Ww + x0c;
        const float* q11 = xb + y1c * Ww + x1c;

#pragma unroll
        for (int ks = 0; ks < 4; ks++) {
#pragma unroll
            for (int kp0 = 0; kp0 < 4; kp0++) {
                const int cA = 16 * ks + 2 * kp0;
                const int cs[4] = { cA, cA + 1, cA + 8, cA + 9 };
                float s[4];
#pragma unroll
                for (int j = 0; j < 4; j++) {
                    const int c = cs[j];
                    float v = __ldg(q00 + c * HW) * c00;
                    v = fmaf(__ldg(q01 + c * HW), c01, v);
                    v = fmaf(__ldg(q10 + c * HW), c10, v);
                    v = fmaf(__ldg(q11 + c * HW), c11, v);
                    s[j] = v;
                }
                float h0, l0, h1, l1, h2, l2, h3, l3;
                bfsplit(s[0], h0, l0); bfsplit(s[1], h1, l1);
                bfsplit(s[2], h2, l2); bfsplit(s[3], h3, l3);
                const int wbase = pix * ROWW + ks * 8 + 2 * (kp0 ^ swzp);
                *(uint2*)&smu[SA_HI + wbase] = make_uint2(bfpack(h0, h1), bfpack(h2, h3));
                *(uint2*)&smu[SA_LO + wbase] = make_uint2(bfpack(l0, l1), bfpack(l2, l3));
            }
        }

        __syncthreads();

#pragma unroll
        for (int ks = 0; ks < 4; ks++) {
            uint32_t ah[2][4], al[2][4];
#pragma unroll
            for (int mt = 0; mt < 2; mt++) {
                const int r0 = warp * 32 + mt * 16 + g;
                const int r1 = r0 + 8;
                const int w0 = r0 * ROWW + ks * 8 + 2 * (tg ^ ((r0 >> 2) & 3));
                const int w1 = r1 * ROWW + ks * 8 + 2 * (tg ^ ((r1 >> 2) & 3));
                uint2 H0 = *(const uint2*)&smu[SA_HI + w0];
                uint2 H1 = *(const uint2*)&smu[SA_HI + w1];
                uint2 L0 = *(const uint2*)&smu[SA_LO + w0];
                uint2 L1 = *(const uint2*)&smu[SA_LO + w1];
                ah[mt][0] = H0.x; ah[mt][1] = H1.x; ah[mt][2] = H0.y; ah[mt][3] = H1.y;
                al[mt][0] = L0.x; al[mt][1] = L1.x; al[mt][2] = L0.y; al[mt][3] = L1.y;
            }
#pragma unroll
            for (int nt = 0; nt < 8; nt++) {
                const int o  = nt * 8 + g;
                const int wb = o * ROWW + ks * 8 + 2 * (tg ^ ((o >> 2) & 3));
                uint2 bh = *(const uint2*)&smu[SB_HI + wb];
                uint2 bl = *(const uint2*)&smu[SB_LO + wb];
#pragma unroll
                for (int mt = 0; mt < 2; mt++) {
                    MMA_BF16(acc[mt][nt], ah[mt], bh.x, bh.y);
                    MMA_BF16(acc[mt][nt], al[mt], bh.x, bh.y);
                    MMA_BF16(acc[mt][nt], ah[mt], bl.x, bl.y);
                }
            }
        }
    }

    float* ob = out + (size_t)b * Oo * HW + row * Ww;
#pragma unroll
    for (int mt = 0; mt < 2; mt++) {
        const int r0 = warp * 32 + mt * 16 + g;
        const int r1 = r0 + 8;
#pragma unroll
        for (int nt = 0; nt < 8; nt++) {
            const int o0 = nt * 8 + tg * 2;
            ob[(o0)     * HW + r0] = acc[mt][nt][0];
            ob[(o0 + 1) * HW + r0] = acc[mt][nt][1];
            ob[(o0)     * HW + r1] = acc[mt][nt][2];
            ob[(o0 + 1) * HW + r1] = acc[mt][nt][3];
        }
    }
}

// ---------------------------------------------------------------------------

extern "C" void kernel_launch(void* const* d_in, const int* in_sizes, int n_in,
                              void* d_out, int out_size)
{
    const float* x     = (const float*)d_in[0];
    const float* omap  = (const float*)d_in[1];
    const float* mmap  = (const float*)d_in[2];
    const float* ow    = (const float*)d_in[3];
    const float* obias = (const float*)d_in[4];
    const float* mw    = (const float*)d_in[5];
    const float* mbias = (const float*)d_in[6];
    const float* w     = (const float*)d_in[7];
    float* out = (float*)d_out;

    const int prep_total = 9 * 2048 + 9 * 768 + 9 * 512;   // 29952
    prep_kernel<<<(prep_total + 255) / 256, 256>>>(w, ow, mw);

    dim3 grid(Bb * Hh);     // 512 blocks, 1 image row each

    const int om_smem = OM_WORDS * (int)sizeof(uint32_t);  // 94720
    cudaFuncSetAttribute(offmask_kernel, cudaFuncAttributeMaxDynamicSharedMemorySize, om_smem);
    offmask_kernel<<<grid, 128, om_smem>>>(omap, mmap, obias, mbias);

    const int df_smem = SM_WORDS * (int)sizeof(uint32_t);  // 61440
    cudaFuncSetAttribute(deform_kernel, cudaFuncAttributeMaxDynamicSharedMemorySize, df_smem);
    deform_kernel<<<grid, 128, df_smem>>>(x, out);
}

// round 11
// speedup vs baseline: 2.8554x; 1.0827x over previous
#include <cuda_runtime.h>
#include <cuda_bf16.h>
#include <math.h>
#include <stdint.h>

#define HW   (128 * 128)
#define Hh   128
#define Ww   128
#define Bb   4
#define Cc   64
#define Oo   64

// Scratch: offsets/mask planes [B][27][H][W]  (0..8 dy_k, 9..17 dx_k, 18..26 mask_k)
__device__ float g_scratch[Bb * 27 * HW];
// Pre-split bf16 B images, exact smem layout. word(o,kp) within a tap image:
//   ks=kp>>3, j=kp&7 -> o*40 + ks*8 + 2*((j&3)^((o>>2)&3)) + (j>>2)
__device__ __align__(16) uint32_t g_wbh[9 * 64 * 40];    // deform weight hi
__device__ __align__(16) uint32_t g_wbl[9 * 64 * 40];    // deform weight lo
__device__ __align__(16) uint32_t g_wboh[9 * 24 * 40];   // offset-conv weight hi (rows 18..23 = 0)
__device__ __align__(16) uint32_t g_wbol[9 * 24 * 40];
__device__ __align__(16) uint32_t g_wbmh[9 * 16 * 40];   // mod-conv weight hi (rows 9..15 = 0)
__device__ __align__(16) uint32_t g_wbml[9 * 16 * 40];

// ---------------- helpers ----------------
__device__ __forceinline__ uint32_t bfpack(float a, float b) {
    __nv_bfloat162 t = __floats2bfloat162_rn(a, b);
    return *(uint32_t*)&t;
}
__device__ __forceinline__ void bfsplit(float s, float &hi, float &lo) {
    hi = __bfloat162float(__float2bfloat16(s));
    lo = s - hi;
}

#define MMA_BF16(d, a, b0, b1) \
    asm volatile("mma.sync.aligned.m16n8k16.row.col.f32.bf16.bf16.f32 " \
        "{%0,%1,%2,%3}, {%4,%5,%6,%7}, {%8,%9}, {%0,%1,%2,%3};" \
        : "+f"((d)[0]), "+f"((d)[1]), "+f"((d)[2]), "+f"((d)[3]) \
        : "r"((a)[0]), "r"((a)[1]), "r"((a)[2]), "r"((a)[3]), "r"(b0), "r"(b1))

__device__ __forceinline__ int swz_word(int o, int kp) {
    int ks = kp >> 3, j = kp & 7;
    return o * 40 + ks * 8 + 2 * ((j & 3) ^ ((o >> 2) & 3)) + (j >> 2);
}

// ---------------------------------------------------------------------------
// Prep: bake all bf16-split swizzled B images.  (unchanged from R10)
// ---------------------------------------------------------------------------
__global__ void prep_kernel(const float* __restrict__ w,
                            const float* __restrict__ ow,
                            const float* __restrict__ mw)
{
    int i = blockIdx.x * 256 + threadIdx.x;
    if (i < 9 * 2048) {                 // deform: 9 x 64 o x 32 kp
        int k  = i >> 11;
        int r  = i & 2047;
        int o  = r >> 5;
        int kp = r & 31;
        int c0 = 2 * kp;
        float v0 = w[o * 576 + c0 * 9 + k];
        float v1 = w[o * 576 + (c0 + 1) * 9 + k];
        float h0, l0, h1, l1;
        bfsplit(v0, h0, l0); bfsplit(v1, h1, l1);
        int word = swz_word(o, kp);
        g_wbh[k * 2560 + word] = bfpack(h0, h1);
        g_wbl[k * 2560 + word] = bfpack(l0, l1);
    }
    int j = i - 9 * 2048;
    if (j >= 0 && j < 9 * 768) {        // offset conv: 9 x 24 o x 32 kp
        int k  = j / 768;
        int r  = j % 768;
        int o  = r >> 5;
        int kp = r & 31;
        int c0 = 2 * kp;
        float v0 = (o < 18) ? ow[o * 576 + c0 * 9 + k] : 0.f;
        float v1 = (o < 18) ? ow[o * 576 + (c0 + 1) * 9 + k] : 0.f;
        float h0, l0, h1, l1;
        bfsplit(v0, h0, l0); bfsplit(v1, h1, l1);
        int word = swz_word(o, kp);
        g_wboh[k * 960 + word] = bfpack(h0, h1);
        g_wbol[k * 960 + word] = bfpack(l0, l1);
    }
    int l = j - 9 * 768;
    if (l >= 0 && l < 9 * 512) {        // mod conv: 9 x 16 o x 32 kp
        int k  = l / 512;
        int r  = l % 512;
        int o  = r >> 5;
        int kp = r & 31;
        int c0 = 2 * kp;
        float v0 = (o < 9) ? mw[o * 576 + c0 * 9 + k] : 0.f;
        float v1 = (o < 9) ? mw[o * 576 + (c0 + 1) * 9 + k] : 0.f;
        float h0, l0, h1, l1;
        bfsplit(v0, h0, l0); bfsplit(v1, h1, l1);
        int word = swz_word(o, kp);
        g_wbmh[k * 640 + word] = bfpack(h0, h1);
        g_wbml[k * 640 + word] = bfpack(l0, l1);
    }
}

// ---------------------------------------------------------------------------
// Kernel 1: offset+mod convs as bf16 MMA GEMMs, HALF-TAP PASSES sharing one
// A tile pair.  Per tap:
//   sync -> stage B + sample omap -> sync -> offset GEMM (D1[128x24])
//   sync -> sample mmap (overwrite A) -> sync -> mod GEMM (D2[128x16])
// Smem 53.8 KB -> 4 CTAs/SM (16 warps/SM, 2x round-10).
// ---------------------------------------------------------------------------
#define ROWW 40
#define A_HI  0
#define A_LO  (A_HI + 128 * ROWW)       //  5120
#define BO_HI (A_LO + 128 * ROWW)       // 10240 (24*40 = 960)
#define BO_LO (BO_HI + 24 * ROWW)       // 11200
#define BM_HI (BO_LO + 24 * ROWW)       // 12160 (16*40 = 640)
#define BM_LO (BM_HI + 16 * ROWW)       // 12800
#define OM_WORDS (BM_LO + 16 * ROWW)    // 13440 words = 53760 B

__global__ __launch_bounds__(128)
void offmask_kernel(const float* __restrict__ omap, const float* __restrict__ mmap,
                    const float* __restrict__ obias, const float* __restrict__ mbias)
{
    extern __shared__ uint32_t smu[];

    const int tid  = threadIdx.x;
    const int lane = tid & 31;
    const int warp = tid >> 5;
    const int g    = lane >> 2;
    const int tg   = lane & 3;

    const int b    = blockIdx.x >> 7;
    const int row  = blockIdx.x & 127;
    const int pix  = tid;
    const int swzp = (pix >> 2) & 3;

    const float* ob = omap + (size_t)b * Cc * HW;
    const float* mb = mmap + (size_t)b * Cc * HW;

    float d1[2][3][4];    // offset GEMM accumulators
    float d2[2][2][4];    // mod GEMM accumulators
#pragma unroll
    for (int mt = 0; mt < 2; mt++) {
#pragma unroll
        for (int nt = 0; nt < 3; nt++)
#pragma unroll
            for (int r = 0; r < 4; r++) d1[mt][nt][r] = 0.f;
#pragma unroll
        for (int nt = 0; nt < 2; nt++)
#pragma unroll
            for (int r = 0; r < 4; r++) d2[mt][nt][r] = 0.f;
    }

#pragma unroll 1
    for (int k = 0; k < 9; k++) {
        const int ki = k / 3, kj = k % 3;
        const int py = row - 1 + ki;
        const int px = pix - 1 + kj;
        const bool valid = ((unsigned)py < (unsigned)Hh) & ((unsigned)px < (unsigned)Ww);

        // ================= PASS 1: offset conv =================
        __syncthreads();   // previous mod GEMM finished reading A

        // stage BOTH B images for this tap (done once, in pass 1)
        {
            const uint4* soh = (const uint4*)&g_wboh[k * 960];
            const uint4* sol = (const uint4*)&g_wbol[k * 960];
            const uint4* smh = (const uint4*)&g_wbmh[k * 640];
            const uint4* sml = (const uint4*)&g_wbml[k * 640];
#pragma unroll
            for (int i = tid; i < 240; i += 128) {
                ((uint4*)&smu[BO_HI])[i] = soh[i];
                ((uint4*)&smu[BO_LO])[i] = sol[i];
            }
#pragma unroll
            for (int i = tid; i < 160; i += 128) {
                ((uint4*)&smu[BM_HI])[i] = smh[i];
                ((uint4*)&smu[BM_LO])[i] = sml[i];
            }
        }

        // sample omap into A tiles
        {
            const float* qo = ob + py * Ww + px;
#pragma unroll
            for (int ks = 0; ks < 4; ks++) {
#pragma unroll
                for (int kp0 = 0; kp0 < 4; kp0++) {
                    const int cA = 16 * ks + 2 * kp0;
                    const int cs[4] = { cA, cA + 1, cA + 8, cA + 9 };
                    float so[4];
#pragma unroll
                    for (int j = 0; j < 4; j++)
                        so[j] = valid ? __ldg(qo + cs[j] * HW) : 0.f;
                    float h[4], l[4];
#pragma unroll
                    for (int j = 0; j < 4; j++) bfsplit(so[j], h[j], l[j]);
                    const int wbase = pix * ROWW + ks * 8 + 2 * (kp0 ^ swzp);
                    *(uint2*)&smu[A_HI + wbase] = make_uint2(bfpack(h[0], h[1]), bfpack(h[2], h[3]));
                    *(uint2*)&smu[A_LO + wbase] = make_uint2(bfpack(l[0], l[1]), bfpack(l[2], l[3]));
                }
            }
        }

        __syncthreads();

        // offset GEMM
#pragma unroll
        for (int ks = 0; ks < 4; ks++) {
            uint32_t ah[2][4], al[2][4];
#pragma unroll
            for (int mt = 0; mt < 2; mt++) {
                const int r0 = warp * 32 + mt * 16 + g;
                const int r1 = r0 + 8;
                const int w0 = r0 * ROWW + ks * 8 + 2 * (tg ^ ((r0 >> 2) & 3));
                const int w1 = r1 * ROWW + ks * 8 + 2 * (tg ^ ((r1 >> 2) & 3));
                uint2 H0 = *(const uint2*)&smu[A_HI + w0];
                uint2 H1 = *(const uint2*)&smu[A_HI + w1];
                uint2 L0 = *(const uint2*)&smu[A_LO + w0];
                uint2 L1 = *(const uint2*)&smu[A_LO + w1];
                ah[mt][0] = H0.x; ah[mt][1] = H1.x; ah[mt][2] = H0.y; ah[mt][3] = H1.y;
                al[mt][0] = L0.x; al[mt][1] = L1.x; al[mt][2] = L0.y; al[mt][3] = L1.y;
            }
#pragma unroll
            for (int nt = 0; nt < 3; nt++) {
                const int o  = nt * 8 + g;
                const int wb = o * ROWW + ks * 8 + 2 * (tg ^ ((o >> 2) & 3));
                uint2 bh = *(const uint2*)&smu[BO_HI + wb];
                uint2 bl = *(const uint2*)&smu[BO_LO + wb];
#pragma unroll
                for (int mt = 0; mt < 2; mt++) {
                    MMA_BF16(d1[mt][nt], ah[mt], bh.x, bh.y);
                    MMA_BF16(d1[mt][nt], al[mt], bh.x, bh.y);
                    MMA_BF16(d1[mt][nt], ah[mt], bl.x, bl.y);
                }
            }
        }

        // ================= PASS 2: mod conv =================
        __syncthreads();   // offset GEMM finished reading A

        {
            const float* qm = mb + py * Ww + px;
#pragma unroll
            for (int ks = 0; ks < 4; ks++) {
#pragma unroll
                for (int kp0 = 0; kp0 < 4; kp0++) {
                    const int cA = 16 * ks + 2 * kp0;
                    const int cs[4] = { cA, cA + 1, cA + 8, cA + 9 };
                    float sm[4];
#pragma unroll
                    for (int j = 0; j < 4; j++)
                        sm[j] = valid ? __ldg(qm + cs[j] * HW) : 0.f;
                    float h[4], l[4];
#pragma unroll
                    for (int j = 0; j < 4; j++) bfsplit(sm[j], h[j], l[j]);
                    const int wbase = pix * ROWW + ks * 8 + 2 * (kp0 ^ swzp);
                    *(uint2*)&smu[A_HI + wbase] = make_uint2(bfpack(h[0], h[1]), bfpack(h[2], h[3]));
                    *(uint2*)&smu[A_LO + wbase] = make_uint2(bfpack(l[0], l[1]), bfpack(l[2], l[3]));
                }
            }
        }

        __syncthreads();

        // mod GEMM
#pragma unroll
        for (int ks = 0; ks < 4; ks++) {
            uint32_t ah[2][4], al[2][4];
#pragma unroll
            for (int mt = 0; mt < 2; mt++) {
                const int r0 = warp * 32 + mt * 16 + g;
                const int r1 = r0 + 8;
                const int w0 = r0 * ROWW + ks * 8 + 2 * (tg ^ ((r0 >> 2) & 3));
                const int w1 = r1 * ROWW + ks * 8 + 2 * (tg ^ ((r1 >> 2) & 3));
                uint2 H0 = *(const uint2*)&smu[A_HI + w0];
                uint2 H1 = *(const uint2*)&smu[A_HI + w1];
                uint2 L0 = *(const uint2*)&smu[A_LO + w0];
                uint2 L1 = *(const uint2*)&smu[A_LO + w1];
                ah[mt][0] = H0.x; ah[mt][1] = H1.x; ah[mt][2] = H0.y; ah[mt][3] = H1.y;
                al[mt][0] = L0.x; al[mt][1] = L1.x; al[mt][2] = L0.y; al[mt][3] = L1.y;
            }
#pragma unroll
            for (int nt = 0; nt < 2; nt++) {
                const int o  = nt * 8 + g;
                const int wb = o * ROWW + ks * 8 + 2 * (tg ^ ((o >> 2) & 3));
                uint2 bh = *(const uint2*)&smu[BM_HI + wb];
                uint2 bl = *(const uint2*)&smu[BM_LO + wb];
#pragma unroll
                for (int mt = 0; mt < 2; mt++) {
                    MMA_BF16(d2[mt][nt], ah[mt], bh.x, bh.y);
                    MMA_BF16(d2[mt][nt], al[mt], bh.x, bh.y);
                    MMA_BF16(d2[mt][nt], ah[mt], bl.x, bl.y);
                }
            }
        }
    }

    // ---- epilogue: fragments -> scratch planes (bias, 2*sigmoid) ----
    float* S = g_scratch + (size_t)b * 27 * HW + row * Ww;
#pragma unroll
    for (int mt = 0; mt < 2; mt++) {
        const int r0 = warp * 32 + mt * 16 + g;
        const int r1 = r0 + 8;
#pragma unroll
        for (int nt = 0; nt < 3; nt++) {
            const int t0 = nt * 8 + tg * 2;
#pragma unroll
            for (int e = 0; e < 2; e++) {
                const int t = t0 + e;
                if (t < 18) {
                    const int plane = (t & 1) ? (9 + (t >> 1)) : (t >> 1);
                    const float bias = __ldg(&obias[t]);
                    S[plane * HW + r0] = d1[mt][nt][e]     + bias;
                    S[plane * HW + r1] = d1[mt][nt][e + 2] + bias;
                }
            }
        }
#pragma unroll
        for (int nt = 0; nt < 2; nt++) {
            const int t0 = nt * 8 + tg * 2;
#pragma unroll
            for (int e = 0; e < 2; e++) {
                const int t = t0 + e;
                if (t < 9) {
                    const float bias = __ldg(&mbias[t]);
                    float z0 = d2[mt][nt][e]     + bias;
                    float z1 = d2[mt][nt][e + 2] + bias;
                    S[(18 + t) * HW + r0] = 2.0f / (1.0f + expf(-z0));
                    S[(18 + t) * HW + r1] = 2.0f / (1.0f + expf(-z1));
                }
            }
        }
    }
}

// ---------------------------------------------------------------------------
// Kernel 2: deformable conv, warp-level bf16 MMA implicit GEMM (R8/R10 form,
// unchanged).
// ---------------------------------------------------------------------------
#define SA_HI 0
#define SA_LO (SA_HI + 128 * ROWW)
#define SB_HI (SA_LO + 128 * ROWW)
#define SB_LO (SB_HI + 64 * ROWW)
#define SM_WORDS (SB_LO + 64 * ROWW)     // 15360 words = 61440 B

__global__ __launch_bounds__(128)
void deform_kernel(const float* __restrict__ x, float* __restrict__ out)
{
    extern __shared__ uint32_t smu[];

    const int tid  = threadIdx.x;
    const int lane = tid & 31;
    const int warp = tid >> 5;
    const int g    = lane >> 2;
    const int tg   = lane & 3;

    const int b   = blockIdx.x >> 7;
    const int row = blockIdx.x & 127;
    const int pix = tid;
    const int p   = row * Ww + pix;
    const int swzp = (pix >> 2) & 3;

    const float* S  = g_scratch + (size_t)b * 27 * HW;
    const float* xb = x + (size_t)b * Cc * HW;

    float acc[2][8][4];
#pragma unroll
    for (int mt = 0; mt < 2; mt++)
#pragma unroll
        for (int nt = 0; nt < 8; nt++)
#pragma unroll
            for (int r = 0; r < 4; r++) acc[mt][nt][r] = 0.f;

#pragma unroll 1
    for (int k = 0; k < 9; k++) {
        __syncthreads();

        {
            const uint4* sh = (const uint4*)&g_wbh[k * 2560];
            const uint4* sl = (const uint4*)&g_wbl[k * 2560];
            uint4* dh = (uint4*)&smu[SB_HI];
            uint4* dl = (uint4*)&smu[SB_LO];
#pragma unroll
            for (int i = tid; i < 640; i += 128) {
                dh[i] = sh[i];
                dl[i] = sl[i];
            }
        }

        const float dy = S[k * HW + p];
        const float dx = S[(9 + k) * HW + p];
        const float m  = S[(18 + k) * HW + p];
        const float py = dy + (float)(row - 1 + k / 3);
        const float px = dx + (float)(pix - 1 + k % 3);
        const float fy = floorf(py), fx = floorf(px);
        const int y0 = (int)fy, x0 = (int)fx;
        const int y1 = y0 + 1,  x1 = x0 + 1;
        const float wy = py - fy, wx = px - fx;

        const bool vy0 = ((unsigned)y0 < (unsigned)Hh);
        const bool vy1 = ((unsigned)y1 < (unsigned)Hh);
        const bool vx0 = ((unsigned)x0 < (unsigned)Ww);
        const bool vx1 = ((unsigned)x1 < (unsigned)Ww);
        const int y0c = min(max(y0, 0), Hh - 1);
        const int y1c = min(max(y1, 0), Hh - 1);
        const int x0c = min(max(x0, 0), Ww - 1);
        const int x1c = min(max(x1, 0), Ww - 1);

        float c00 = (1.f - wy) * (1.f - wx) * m; c00 = (vy0 & vx0) ? c00 : 0.f;
        float c01 = (1.f - wy) * wx         * m; c01 = (vy0 & vx1) ? c01 : 0.f;
        float c10 = wy * (1.f - wx)         * m; c10 = (vy1 & vx0) ? c10 : 0.f;
        float c11 = wy * wx                 * m; c11 = (vy1 & vx1) ? c11 : 0.f;

        const float* q00 = xb + y0c * Ww + x0c;
        const float* q01 = xb + y0c * Ww + x1c;
        const float* q10 = xb + y1c * Ww + x0c;
        const float* q11 = xb + y1c * Ww + x1c;

#pragma unroll
        for (int ks = 0; ks < 4; ks++) {
#pragma unroll
            for (int kp0 = 0; kp0 < 4; kp0++) {
                const int cA = 16 * ks + 2 * kp0;
                const int cs[4] = { cA, cA + 1, cA + 8, cA + 9 };
                float s[4];
#pragma unroll
                for (int j = 0; j < 4; j++) {
                    const int c = cs[j];
                    float v = __ldg(q00 + c * HW) * c00;
                    v = fmaf(__ldg(q01 + c * HW), c01, v);
                    v = fmaf(__ldg(q10 + c * HW), c10, v);
                    v = fmaf(__ldg(q11 + c * HW), c11, v);
                    s[j] = v;
                }
                float h0, l0, h1, l1, h2, l2, h3, l3;
                bfsplit(s[0], h0, l0); bfsplit(s[1], h1, l1);
                bfsplit(s[2], h2, l2); bfsplit(s[3], h3, l3);
                const int wbase = pix * ROWW + ks * 8 + 2 * (kp0 ^ swzp);
                *(uint2*)&smu[SA_HI + wbase] = make_uint2(bfpack(h0, h1), bfpack(h2, h3));
                *(uint2*)&smu[SA_LO + wbase] = make_uint2(bfpack(l0, l1), bfpack(l2, l3));
            }
        }

        __syncthreads();

#pragma unroll
        for (int ks = 0; ks < 4; ks++) {
            uint32_t ah[2][4], al[2][4];
#pragma unroll
            for (int mt = 0; mt < 2; mt++) {
                const int r0 = warp * 32 + mt * 16 + g;
                const int r1 = r0 + 8;
                const int w0 = r0 * ROWW + ks * 8 + 2 * (tg ^ ((r0 >> 2) & 3));
                const int w1 = r1 * ROWW + ks * 8 + 2 * (tg ^ ((r1 >> 2) & 3));
                uint2 H0 = *(const uint2*)&smu[SA_HI + w0];
                uint2 H1 = *(const uint2*)&smu[SA_HI + w1];
                uint2 L0 = *(const uint2*)&smu[SA_LO + w0];
                uint2 L1 = *(const uint2*)&smu[SA_LO + w1];
                ah[mt][0] = H0.x; ah[mt][1] = H1.x; ah[mt][2] = H0.y; ah[mt][3] = H1.y;
                al[mt][0] = L0.x; al[mt][1] = L1.x; al[mt][2] = L0.y; al[mt][3] = L1.y;
            }
#pragma unroll
            for (int nt = 0; nt < 8; nt++) {
                const int o  = nt * 8 + g;
                const int wb = o * ROWW + ks * 8 + 2 * (tg ^ ((o >> 2) & 3));
                uint2 bh = *(const uint2*)&smu[SB_HI + wb];
                uint2 bl = *(const uint2*)&smu[SB_LO + wb];
#pragma unroll
                for (int mt = 0; mt < 2; mt++) {
                    MMA_BF16(acc[mt][nt], ah[mt], bh.x, bh.y);
                    MMA_BF16(acc[mt][nt], al[mt], bh.x, bh.y);
                    MMA_BF16(acc[mt][nt], ah[mt], bl.x, bl.y);
                }
            }
        }
    }

    float* ob = out + (size_t)b * Oo * HW + row * Ww;
#pragma unroll
    for (int mt = 0; mt < 2; mt++) {
        const int r0 = warp * 32 + mt * 16 + g;
        const int r1 = r0 + 8;
#pragma unroll
        for (int nt = 0; nt < 8; nt++) {
            const int o0 = nt * 8 + tg * 2;
            ob[(o0)     * HW + r0] = acc[mt][nt][0];
            ob[(o0 + 1) * HW + r0] = acc[mt][nt][1];
            ob[(o0)     * HW + r1] = acc[mt][nt][2];
            ob[(o0 + 1) * HW + r1] = acc[mt][nt][3];
        }
    }
}

// ---------------------------------------------------------------------------

extern "C" void kernel_launch(void* const* d_in, const int* in_sizes, int n_in,
                              void* d_out, int out_size)
{
    const float* x     = (const float*)d_in[0];
    const float* omap  = (const float*)d_in[1];
    const float* mmap  = (const float*)d_in[2];
    const float* ow    = (const float*)d_in[3];
    const float* obias = (const float*)d_in[4];
    const float* mw    = (const float*)d_in[5];
    const float* mbias = (const float*)d_in[6];
    const float* w     = (const float*)d_in[7];
    float* out = (float*)d_out;

    const int prep_total = 9 * 2048 + 9 * 768 + 9 * 512;   // 29952
    prep_kernel<<<(prep_total + 255) / 256, 256>>>(w, ow, mw);

    dim3 grid(Bb * Hh);     // 512 blocks, 1 image row each

    const int om_smem = OM_WORDS * (int)sizeof(uint32_t);  // 53760
    cudaFuncSetAttribute(offmask_kernel, cudaFuncAttributeMaxDynamicSharedMemorySize, om_smem);
    offmask_kernel<<<grid, 128, om_smem>>>(omap, mmap, obias, mbias);

    const int df_smem = SM_WORDS * (int)sizeof(uint32_t);  // 61440
    cudaFuncSetAttribute(deform_kernel, cudaFuncAttributeMaxDynamicSharedMemorySize, df_smem);
    deform_kernel<<<grid, 128, df_smem>>>(x, out);
}